// round 12
// baseline (speedup 1.0000x reference)
#include <cuda_runtime.h>
#include <cuda_bf16.h>
#include <cstdint>

#define B_   512
#define L_   256
#define D_   128
#define EPSF 0.01f
#define NW   24             // warps per CTA
#define NT   768            // threads per CTA
#define SRSB 272            // bf16 row stride in bytes: ldmatrix conflict-free
#define HLOFF 69632         // byte offset from HH to HL

// ---- smem byte offsets ----
#define SM_HH   0           // 256 x SRSB bf16 high split
#define SM_HL   69632       // low split
#define SM_INV  139264      // 256 f32
#define SM_M    140288      // 256 f32 key mask
#define SM_SEL  141312      // 256 f32 (mask*last)
#define SM_A    142336      // 256 f32 a_i = sel_i / wsum_i
#define SM_WSP  143360      // 24 x 256 f32 per-warp wsum partials
#define SM_VPT  167936      // 24 x 256 f32 per-warp v partials
#define SM_DP   192512      // 24 x 128 f32 direct-term partials
#define SM_ACC  204800      // 512 f32
#define SM_TOT  206848
// cross-phase aliases (H region dead by then)
#define CX_HL   0           // 128 f32
#define CX_WS   512         // 24 f32
#define CX_HA   1024        // 24 x 128 f32
#define CX_HV   13312       // 128 f32
#define CX_IQ   13824       // 1 f32

// packed (tr<<4 | tc) for upper-triangular job index j in [0,136)
__device__ __constant__ unsigned char TRTAB[136] = {
    0x00,0x01,0x02,0x03,0x04,0x05,0x06,0x07,0x08,0x09,0x0A,0x0B,0x0C,0x0D,0x0E,0x0F,
    0x11,0x12,0x13,0x14,0x15,0x16,0x17,0x18,0x19,0x1A,0x1B,0x1C,0x1D,0x1E,0x1F,
    0x22,0x23,0x24,0x25,0x26,0x27,0x28,0x29,0x2A,0x2B,0x2C,0x2D,0x2E,0x2F,
    0x33,0x34,0x35,0x36,0x37,0x38,0x39,0x3A,0x3B,0x3C,0x3D,0x3E,0x3F,
    0x44,0x45,0x46,0x47,0x48,0x49,0x4A,0x4B,0x4C,0x4D,0x4E,0x4F,
    0x55,0x56,0x57,0x58,0x59,0x5A,0x5B,0x5C,0x5D,0x5E,0x5F,
    0x66,0x67,0x68,0x69,0x6A,0x6B,0x6C,0x6D,0x6E,0x6F,
    0x77,0x78,0x79,0x7A,0x7B,0x7C,0x7D,0x7E,0x7F,
    0x88,0x89,0x8A,0x8B,0x8C,0x8D,0x8E,0x8F,
    0x99,0x9A,0x9B,0x9C,0x9D,0x9E,0x9F,
    0xAA,0xAB,0xAC,0xAD,0xAE,0xAF,
    0xBB,0xBC,0xBD,0xBE,0xBF,
    0xCC,0xCD,0xCE,0xCF,
    0xDD,0xDE,0xDF,
    0xEE,0xEF,
    0xFF
};

__device__ __forceinline__ uint32_t smem_u32(const void* p) {
    uint32_t a;
    asm("{ .reg .u64 t; cvta.to.shared.u64 t, %1; cvt.u32.u64 %0, t; }" : "=r"(a) : "l"(p));
    return a;
}
#define LDSM4(r, addr) \
    asm volatile("ldmatrix.sync.aligned.m8n8.x4.shared.b16 {%0,%1,%2,%3}, [%4];" \
        : "=r"((r)[0]), "=r"((r)[1]), "=r"((r)[2]), "=r"((r)[3]) : "r"(addr))
#define MMA16816(c, a, b0, b1) \
    asm volatile("mma.sync.aligned.m16n8k16.row.col.f32.bf16.bf16.f32 " \
        "{%0,%1,%2,%3}, {%4,%5,%6,%7}, {%8,%9}, {%0,%1,%2,%3};" \
        : "+f"((c)[0]), "+f"((c)[1]), "+f"((c)[2]), "+f"((c)[3]) \
        : "r"((a)[0]), "r"((a)[1]), "r"((a)[2]), "r"((a)[3]), "r"(b0), "r"(b1))
#define BFLY(x, o) x += __shfl_xor_sync(0xffffffffu, x, o)

// compute e[8] = exp(cos) for 16x16 tile (tr,tc); bit-identical on recompute
__device__ __forceinline__ void tile_e(uint32_t sb, int tr, int tc, int lane,
                                       const float* invv, float* e)
{
    float a1r[8], a2r[8];
    #pragma unroll
    for (int i = 0; i < 8; ++i) { e[i] = 0.f; a1r[i] = 0.f; a2r[i] = 0.f; }

    const uint32_t aH = sb + SM_HH
        + (uint32_t)(tr * 16 + (lane & 7) + (((lane >> 3) & 1) * 8)) * SRSB
        + (uint32_t)((lane >> 4) * 8) * 2;
    const uint32_t bH = sb + SM_HH
        + (uint32_t)(tc * 16 + (lane & 7) + ((lane >> 4) * 8)) * SRSB
        + (uint32_t)((lane >> 3) & 1) * 16;

    #pragma unroll 2
    for (int k = 0; k < 8; ++k) {
        uint32_t ah[4], al[4], bh[4], bl[4];
        LDSM4(ah, aH + k * 32);
        LDSM4(al, aH + HLOFF + k * 32);
        LDSM4(bh, bH + k * 32);
        LDSM4(bl, bH + HLOFF + k * 32);
        MMA16816(e,       ah, bh[0], bh[1]);
        MMA16816(e + 4,   ah, bh[2], bh[3]);
        MMA16816(a1r,     al, bh[0], bh[1]);
        MMA16816(a1r + 4, al, bh[2], bh[3]);
        MMA16816(a2r,     ah, bl[0], bl[1]);
        MMA16816(a2r + 4, ah, bl[2], bl[3]);
    }
    #pragma unroll
    for (int i = 0; i < 8; ++i) e[i] += a1r[i] + a2r[i];

    const int r0 = tr * 16 + (lane >> 2), r1 = r0 + 8;
    const int c0 = tc * 16 + (lane & 3) * 2;
    const float ir0 = invv[r0], ir1 = invv[r1];
    const float ic0 = invv[c0], ic1 = invv[c0 + 1];
    const float ic8 = invv[c0 + 8], ic9 = invv[c0 + 9];
    e[0] = __expf(e[0] * ir0 * ic0); e[1] = __expf(e[1] * ir0 * ic1);
    e[2] = __expf(e[2] * ir1 * ic0); e[3] = __expf(e[3] * ir1 * ic1);
    e[4] = __expf(e[4] * ir0 * ic8); e[5] = __expf(e[5] * ir0 * ic9);
    e[6] = __expf(e[6] * ir1 * ic8); e[7] = __expf(e[7] * ir1 * ic9);
}

__global__ __launch_bounds__(NT, 1)
void fused_itd(const int* __restrict__ seq, const int* __restrict__ last,
               const int* __restrict__ seq1, const float* __restrict__ h1,
               const float* __restrict__ h2, const float* __restrict__ W,
               float* __restrict__ out)
{
    extern __shared__ unsigned char smraw[];
    float* smf = (float*)smraw;
    unsigned char* smc = smraw;
    const uint32_t sb = smem_u32(smraw);
    const int b = blockIdx.x, tid = threadIdx.x, wid = tid >> 5, lane = tid & 31;

    float* invv = smf + SM_INV / 4;
    float* mz   = smf + SM_M / 4;
    float* selv = smf + SM_SEL / 4;
    float* av   = smf + SM_A / 4;
    float* wsp  = smf + SM_WSP / 4;
    float* vpt  = smf + SM_VPT / 4;

    // ---- masks / zero-init of partial arrays ----
    if (tid < 256) {
        int sv = seq[b * L_ + tid], lv = last[b * L_ + tid];
        float m = (sv != 0) ? 1.f : 0.f;
        mz[tid]   = m;
        selv[tid] = m * (float)lv;
    }
    for (int i = tid; i < 2 * NW * 256; i += NT) wsp[i] = 0.f;   // wsp + vpt contiguous
    __syncthreads();

    // ---- load hist_1[b]: split to bf16 hi/lo, norms, direct sel*h term ----
    const float4* src4 = (const float4*)(h1 + (size_t)b * L_ * D_);
    const int d0 = lane * 4;
    float ds0 = 0.f, ds1 = 0.f, ds2 = 0.f, ds3 = 0.f;
    for (int i = wid; i < 256; i += NW) {
        const float4 v = src4[i * 32 + lane];
        float np = v.x * v.x + v.y * v.y + v.z * v.z + v.w * v.w;
        #pragma unroll
        for (int o = 16; o; o >>= 1) np += __shfl_xor_sync(0xffffffffu, np, o);
        if (lane == 0) invv[i] = rsqrtf(np + EPSF);
        const float se = selv[i];
        ds0 += se * v.x; ds1 += se * v.y; ds2 += se * v.z; ds3 += se * v.w;

        float xs[4] = { v.x, v.y, v.z, v.w };
        uint16_t hh[4], hl[4];
        #pragma unroll
        for (int j = 0; j < 4; ++j) {
            __nv_bfloat16 hb = __float2bfloat16_rn(xs[j]);
            __nv_bfloat16 lb = __float2bfloat16_rn(xs[j] - __bfloat162float(hb));
            hh[j] = __nv_bfloat16_raw(hb).x;
            hl[j] = __nv_bfloat16_raw(lb).x;
        }
        uint32_t off = (uint32_t)i * SRSB + (uint32_t)d0 * 2;
        *(uint2*)(smc + SM_HH + off) = make_uint2(
            (uint32_t)hh[0] | ((uint32_t)hh[1] << 16), (uint32_t)hh[2] | ((uint32_t)hh[3] << 16));
        *(uint2*)(smc + SM_HL + off) = make_uint2(
            (uint32_t)hl[0] | ((uint32_t)hl[1] << 16), (uint32_t)hl[2] | ((uint32_t)hl[3] << 16));
    }
    smf[SM_DP / 4 + wid * D_ + d0 + 0] = ds0;
    smf[SM_DP / 4 + wid * D_ + d0 + 1] = ds1;
    smf[SM_DP / 4 + wid * D_ + d0 + 2] = ds2;
    smf[SM_DP / 4 + wid * D_ + d0 + 3] = ds3;
    __syncthreads();

    // =======================================================================
    // Self attention on upper-triangular 16x16 tiles (136 jobs, 24 warps).
    // Phase 2 recomputes e (bit-identical) instead of caching in registers.
    // =======================================================================

    // ---- phase 1: wsum contributions (rows direct, cols mirror) ----
    #pragma unroll
    for (int t = 0; t < 6; ++t) {
        const int j = wid + NW * t;
        if (j < 136) {
            const int pk = TRTAB[j];
            const int tr = pk >> 4, tc = pk & 15;
            float e[8];
            tile_e(sb, tr, tc, lane, invv, e);

            const int r0 = tr * 16 + (lane >> 2), r1 = r0 + 8;
            const int c0 = tc * 16 + (lane & 3) * 2;

            // direct: ws[r] += sum_c e*m_c
            const float mc0 = mz[c0], mc1 = mz[c0 + 1], mc8 = mz[c0 + 8], mc9 = mz[c0 + 9];
            float rs0 = e[0] * mc0 + e[1] * mc1 + e[4] * mc8 + e[5] * mc9;
            float rs1 = e[2] * mc0 + e[3] * mc1 + e[6] * mc8 + e[7] * mc9;
            BFLY(rs0, 1); BFLY(rs0, 2);
            BFLY(rs1, 1); BFLY(rs1, 2);
            if ((lane & 3) == 0) {
                wsp[wid * 256 + r0] += rs0;
                wsp[wid * 256 + r1] += rs1;
            }
            // mirror: ws[c] += sum_r e*m_r  (skip on diagonal tiles)
            if (tr != tc) {
                const float mr0 = mz[r0], mr1 = mz[r1];
                float cs0 = e[0] * mr0 + e[2] * mr1;
                float cs1 = e[1] * mr0 + e[3] * mr1;
                float cs8 = e[4] * mr0 + e[6] * mr1;
                float cs9 = e[5] * mr0 + e[7] * mr1;
                BFLY(cs0, 4); BFLY(cs0, 8); BFLY(cs0, 16);
                BFLY(cs1, 4); BFLY(cs1, 8); BFLY(cs1, 16);
                BFLY(cs8, 4); BFLY(cs8, 8); BFLY(cs8, 16);
                BFLY(cs9, 4); BFLY(cs9, 8); BFLY(cs9, 16);
                if (lane < 4) {
                    const int cb = tc * 16 + lane * 2;
                    wsp[wid * 256 + cb]     += cs0;
                    wsp[wid * 256 + cb + 1] += cs1;
                    wsp[wid * 256 + cb + 8] += cs8;
                    wsp[wid * 256 + cb + 9] += cs9;
                }
            }
        }
    }
    __syncthreads();

    // ---- a_i = sel_i / wsum_i ----
    if (tid < 256) {
        float ws = 0.f;
        #pragma unroll
        for (int w = 0; w < NW; ++w) ws += wsp[w * 256 + tid];
        av[tid] = selv[tid] / ws;
    }
    __syncthreads();

    // ---- phase 2: v contributions (cols direct, rows mirror), recompute e ----
    #pragma unroll
    for (int t = 0; t < 6; ++t) {
        const int j = wid + NW * t;
        if (j < 136) {
            const int pk = TRTAB[j];
            const int tr = pk >> 4, tc = pk & 15;
            float e[8];
            tile_e(sb, tr, tc, lane, invv, e);

            const int r0 = tr * 16 + (lane >> 2), r1 = r0 + 8;
            const int c0 = tc * 16 + (lane & 3) * 2;

            // direct: v[c] += m_c * sum_r a_r e_rc
            const float ar0 = av[r0], ar1 = av[r1];
            float pc0 = ar0 * e[0] + ar1 * e[2];
            float pc1 = ar0 * e[1] + ar1 * e[3];
            float pc8 = ar0 * e[4] + ar1 * e[6];
            float pc9 = ar0 * e[5] + ar1 * e[7];
            BFLY(pc0, 4); BFLY(pc0, 8); BFLY(pc0, 16);
            BFLY(pc1, 4); BFLY(pc1, 8); BFLY(pc1, 16);
            BFLY(pc8, 4); BFLY(pc8, 8); BFLY(pc8, 16);
            BFLY(pc9, 4); BFLY(pc9, 8); BFLY(pc9, 16);
            if (lane < 4) {
                const int cb = tc * 16 + lane * 2;
                vpt[wid * 256 + cb]     += pc0 * mz[cb];
                vpt[wid * 256 + cb + 1] += pc1 * mz[cb + 1];
                vpt[wid * 256 + cb + 8] += pc8 * mz[cb + 8];
                vpt[wid * 256 + cb + 9] += pc9 * mz[cb + 9];
            }
            // mirror: v[r] += m_r * sum_c a_c e_rc  (skip on diagonal tiles)
            if (tr != tc) {
                const float ac0 = av[c0], ac1 = av[c0 + 1];
                const float ac8 = av[c0 + 8], ac9 = av[c0 + 9];
                float qr0 = ac0 * e[0] + ac1 * e[1] + ac8 * e[4] + ac9 * e[5];
                float qr1 = ac0 * e[2] + ac1 * e[3] + ac8 * e[6] + ac9 * e[7];
                BFLY(qr0, 1); BFLY(qr0, 2);
                BFLY(qr1, 1); BFLY(qr1, 2);
                if ((lane & 3) == 0) {
                    vpt[wid * 256 + r0] += qr0 * mz[r0];
                    vpt[wid * 256 + r1] += qr1 * mz[r1];
                }
            }
        }
    }
    __syncthreads();

    // ---- v = sum of warp partials ----
    if (tid < 256) {
        float v = 0.f;
        #pragma unroll
        for (int w = 0; w < NW; ++w) v += vpt[w * 256 + tid];
        vpt[tid] = v;   // own slot only: no race
    }
    __syncthreads();

    // ---- acc[d] = sum_j v_j * (Hh[j,d] + Hl[j,d]), 4-way split over j ----
    if (tid < 512) {
        const int d = tid & 127, jb = (tid >> 7) * 64;
        float a = 0.f;
        #pragma unroll 4
        for (int jx = 0; jx < 64; ++jx) {
            const int j = jb + jx;
            const float vj = vpt[j];
            const uint32_t off = (uint32_t)j * SRSB + (uint32_t)d * 2;
            float hv = __bfloat162float(*(__nv_bfloat16*)(smc + SM_HH + off))
                     + __bfloat162float(*(__nv_bfloat16*)(smc + SM_HL + off));
            a += vj * hv;
        }
        smf[SM_ACC / 4 + tid] = a;
    }
    __syncthreads();
    if (tid < D_) {   // h_last -> CX_HL (H region dead after the sync above)
        float s = smf[SM_ACC / 4 + tid] + smf[SM_ACC / 4 + 128 + tid]
                + smf[SM_ACC / 4 + 256 + tid] + smf[SM_ACC / 4 + 384 + tid];
        #pragma unroll
        for (int w = 0; w < NW; ++w) s += smf[SM_DP / 4 + w * D_ + tid];
        smf[CX_HL / 4 + tid] = s;
    }
    __syncthreads();

    // ---- cross cosine-attention over hist_2 + relu(h @ W) ----
    if (tid < 32) {
        float s = 0.f;
        #pragma unroll
        for (int c = 0; c < 4; ++c) { float v = smf[CX_HL / 4 + tid + 32 * c]; s += v * v; }
        #pragma unroll
        for (int o = 16; o; o >>= 1) s += __shfl_xor_sync(0xffffffffu, s, o);
        if (tid == 0) smf[CX_IQ / 4] = rsqrtf(s + EPSF);
    }
    __syncthreads();
    {
        const float invq = smf[CX_IQ / 4];
        const float* H2 = h2 + (size_t)b * 256 * D_;
        const float q0 = smf[CX_HL / 4 + lane * 4],     q1 = smf[CX_HL / 4 + lane * 4 + 1];
        const float q2 = smf[CX_HL / 4 + lane * 4 + 2], q3 = smf[CX_HL / 4 + lane * 4 + 3];
        float a0 = 0.f, a1 = 0.f, a2 = 0.f, a3 = 0.f, wp = 0.f;
        for (int k = wid; k < 256; k += NW) {
            float4 v = ((const float4*)(H2 + k * D_))[lane];
            float dot = v.x * q0 + v.y * q1 + v.z * q2 + v.w * q3;
            float nk  = v.x * v.x + v.y * v.y + v.z * v.z + v.w * v.w;
            #pragma unroll
            for (int o = 16; o; o >>= 1) {
                dot += __shfl_xor_sync(0xffffffffu, dot, o);
                nk  += __shfl_xor_sync(0xffffffffu, nk,  o);
            }
            float w = __expf(dot * rsqrtf(nk + EPSF) * invq)
                    * ((seq1[b * 256 + k] != 0) ? 1.f : 0.f);
            wp += w;
            a0 += w * v.x; a1 += w * v.y; a2 += w * v.z; a3 += w * v.w;
        }
        if (lane == 0) smf[CX_WS / 4 + wid] = wp;
        smf[CX_HA / 4 + wid * D_ + lane * 4]     = a0;
        smf[CX_HA / 4 + wid * D_ + lane * 4 + 1] = a1;
        smf[CX_HA / 4 + wid * D_ + lane * 4 + 2] = a2;
        smf[CX_HA / 4 + wid * D_ + lane * 4 + 3] = a3;
    }
    __syncthreads();
    if (tid < D_) {
        float ws = 0.f, s = 0.f;
        #pragma unroll
        for (int w = 0; w < NW; ++w) { ws += smf[CX_WS / 4 + w]; s += smf[CX_HA / 4 + w * D_ + tid]; }
        smf[CX_HV / 4 + tid] = s / ws;
    }
    __syncthreads();

    // ---- out = relu(hv @ W), 4-way split over d then combine ----
    if (tid < 512) {
        const int col = tid & 127, q = tid >> 7;
        float o = 0.f;
        #pragma unroll 8
        for (int dx = 0; dx < 32; ++dx) {
            const int d = q * 32 + dx;
            o += smf[CX_HV / 4 + d] * W[d * D_ + col];
        }
        smf[CX_HA / 4 + q * D_ + col] = o;   // reuse CX_HA (dead after hv combine)
    }
    __syncthreads();
    if (tid < D_) {
        float o = smf[CX_HA / 4 + tid] + smf[CX_HA / 4 + 128 + tid]
                + smf[CX_HA / 4 + 256 + tid] + smf[CX_HA / 4 + 384 + tid];
        out[b * D_ + tid] = fmaxf(o, 0.f);
    }
}

extern "C" void kernel_launch(void* const* d_in, const int* in_sizes, int n_in,
                              void* d_out, int out_size)
{
    const int*   seq  = (const int*)d_in[0];
    const int*   last = (const int*)d_in[1];
    const int*   seq1 = (const int*)d_in[2];
    const float* h1   = (const float*)d_in[3];
    const float* h2   = (const float*)d_in[4];
    const float* W    = (const float*)d_in[5];
    float* out = (float*)d_out;

    cudaFuncSetAttribute(fused_itd, cudaFuncAttributeMaxDynamicSharedMemorySize, SM_TOT);
    fused_itd<<<B_, NT, SM_TOT>>>(seq, last, seq1, h1, h2, W, out);
}

// round 13
// speedup vs baseline: 1.2376x; 1.2376x over previous
#include <cuda_runtime.h>
#include <cuda_bf16.h>
#include <cstdint>

#define B_   512
#define L_   256
#define D_   128
#define EPSF 0.01f
#define NW   20             // warps per CTA
#define NT   640            // threads per CTA
#define SRSB 272            // bf16 row stride in bytes: ldmatrix conflict-free
#define HLOFF 69632         // byte offset from HH to HL

// ---- smem byte offsets ----
#define SM_HH   0           // 256 x SRSB bf16 high split
#define SM_HL   69632       // low split
#define SM_INV  139264      // 256 f32
#define SM_M    140288      // 256 f32 key mask
#define SM_SEL  141312      // 256 f32 (mask*last)
#define SM_A    142336      // 256 f32 a_i = sel_i / wsum_i
#define SM_WSP  143360      // 20 x 256 f32 per-warp wsum partials
#define SM_VPT  163840      // 20 x 256 f32 per-warp v partials
#define SM_DP   184320      // 20 x 128 f32 direct-term partials
#define SM_ACC  194560      // 512 f32
#define SM_TOT  196608
// cross-phase aliases (H region dead by then)
#define CX_HL   0           // 128 f32
#define CX_WS   512         // 20 f32
#define CX_HA   1024        // 20 x 128 f32
#define CX_HV   11264       // 128 f32
#define CX_IQ   11776       // 1 f32

// packed (tr<<4 | tc) for upper-triangular job index j in [0,136)
__device__ __constant__ unsigned char TRTAB[136] = {
    0x00,0x01,0x02,0x03,0x04,0x05,0x06,0x07,0x08,0x09,0x0A,0x0B,0x0C,0x0D,0x0E,0x0F,
    0x11,0x12,0x13,0x14,0x15,0x16,0x17,0x18,0x19,0x1A,0x1B,0x1C,0x1D,0x1E,0x1F,
    0x22,0x23,0x24,0x25,0x26,0x27,0x28,0x29,0x2A,0x2B,0x2C,0x2D,0x2E,0x2F,
    0x33,0x34,0x35,0x36,0x37,0x38,0x39,0x3A,0x3B,0x3C,0x3D,0x3E,0x3F,
    0x44,0x45,0x46,0x47,0x48,0x49,0x4A,0x4B,0x4C,0x4D,0x4E,0x4F,
    0x55,0x56,0x57,0x58,0x59,0x5A,0x5B,0x5C,0x5D,0x5E,0x5F,
    0x66,0x67,0x68,0x69,0x6A,0x6B,0x6C,0x6D,0x6E,0x6F,
    0x77,0x78,0x79,0x7A,0x7B,0x7C,0x7D,0x7E,0x7F,
    0x88,0x89,0x8A,0x8B,0x8C,0x8D,0x8E,0x8F,
    0x99,0x9A,0x9B,0x9C,0x9D,0x9E,0x9F,
    0xAA,0xAB,0xAC,0xAD,0xAE,0xAF,
    0xBB,0xBC,0xBD,0xBE,0xBF,
    0xCC,0xCD,0xCE,0xCF,
    0xDD,0xDE,0xDF,
    0xEE,0xEF,
    0xFF
};

__device__ __forceinline__ uint32_t smem_u32(const void* p) {
    uint32_t a;
    asm("{ .reg .u64 t; cvta.to.shared.u64 t, %1; cvt.u32.u64 %0, t; }" : "=r"(a) : "l"(p));
    return a;
}
#define LDSM4(r, addr) \
    asm volatile("ldmatrix.sync.aligned.m8n8.x4.shared.b16 {%0,%1,%2,%3}, [%4];" \
        : "=r"((r)[0]), "=r"((r)[1]), "=r"((r)[2]), "=r"((r)[3]) : "r"(addr))
#define MMA16816(c, a, b0, b1) \
    asm volatile("mma.sync.aligned.m16n8k16.row.col.f32.bf16.bf16.f32 " \
        "{%0,%1,%2,%3}, {%4,%5,%6,%7}, {%8,%9}, {%0,%1,%2,%3};" \
        : "+f"((c)[0]), "+f"((c)[1]), "+f"((c)[2]), "+f"((c)[3]) \
        : "r"((a)[0]), "r"((a)[1]), "r"((a)[2]), "r"((a)[3]), "r"(b0), "r"(b1))
#define BFLY(x, o) x += __shfl_xor_sync(0xffffffffu, x, o)

__global__ __launch_bounds__(NT, 1)
void fused_itd(const int* __restrict__ seq, const int* __restrict__ last,
               const int* __restrict__ seq1, const float* __restrict__ h1,
               const float* __restrict__ h2, const float* __restrict__ W,
               float* __restrict__ out)
{
    extern __shared__ unsigned char smraw[];
    float* smf = (float*)smraw;
    unsigned char* smc = smraw;
    const uint32_t sb = smem_u32(smraw);
    const int b = blockIdx.x, tid = threadIdx.x, wid = tid >> 5, lane = tid & 31;

    float* invv = smf + SM_INV / 4;
    float* mz   = smf + SM_M / 4;
    float* selv = smf + SM_SEL / 4;
    float* av   = smf + SM_A / 4;
    float* wsp  = smf + SM_WSP / 4;
    float* vpt  = smf + SM_VPT / 4;

    // ---- masks / zero-init of partial arrays ----
    if (tid < 256) {
        int sv = seq[b * L_ + tid], lv = last[b * L_ + tid];
        float m = (sv != 0) ? 1.f : 0.f;
        mz[tid]   = m;
        selv[tid] = m * (float)lv;
    }
    for (int i = tid; i < 2 * NW * 256; i += NT) wsp[i] = 0.f;   // wsp + vpt contiguous
    __syncthreads();

    // ---- load hist_1[b]: split to bf16 hi/lo, norms, direct sel*h term ----
    const float4* src4 = (const float4*)(h1 + (size_t)b * L_ * D_);
    const int d0 = lane * 4;
    float ds0 = 0.f, ds1 = 0.f, ds2 = 0.f, ds3 = 0.f;
    for (int i = wid; i < 256; i += NW) {
        const float4 v = src4[i * 32 + lane];
        float np = v.x * v.x + v.y * v.y + v.z * v.z + v.w * v.w;
        #pragma unroll
        for (int o = 16; o; o >>= 1) np += __shfl_xor_sync(0xffffffffu, np, o);
        if (lane == 0) invv[i] = rsqrtf(np + EPSF);
        const float se = selv[i];
        ds0 += se * v.x; ds1 += se * v.y; ds2 += se * v.z; ds3 += se * v.w;

        float xs[4] = { v.x, v.y, v.z, v.w };
        uint16_t hh[4], hl[4];
        #pragma unroll
        for (int j = 0; j < 4; ++j) {
            __nv_bfloat16 hb = __float2bfloat16_rn(xs[j]);
            __nv_bfloat16 lb = __float2bfloat16_rn(xs[j] - __bfloat162float(hb));
            hh[j] = __nv_bfloat16_raw(hb).x;
            hl[j] = __nv_bfloat16_raw(lb).x;
        }
        uint32_t off = (uint32_t)i * SRSB + (uint32_t)d0 * 2;
        *(uint2*)(smc + SM_HH + off) = make_uint2(
            (uint32_t)hh[0] | ((uint32_t)hh[1] << 16), (uint32_t)hh[2] | ((uint32_t)hh[3] << 16));
        *(uint2*)(smc + SM_HL + off) = make_uint2(
            (uint32_t)hl[0] | ((uint32_t)hl[1] << 16), (uint32_t)hl[2] | ((uint32_t)hl[3] << 16));
    }
    smf[SM_DP / 4 + wid * D_ + d0 + 0] = ds0;
    smf[SM_DP / 4 + wid * D_ + d0 + 1] = ds1;
    smf[SM_DP / 4 + wid * D_ + d0 + 2] = ds2;
    smf[SM_DP / 4 + wid * D_ + d0 + 3] = ds3;
    __syncthreads();

    // =======================================================================
    // Self attention on upper-triangular 16x16 tiles (136 jobs, 20 warps).
    // Each warp owns a CONTIGUOUS run of <=7 tiles; k-outer / slot-inner
    // phase 1 reuses the A fragment across same-row-block slots.
    // =======================================================================
    const int lo  = (wid < 16) ? wid * 7 : 112 + (wid - 16) * 6;
    const int len = (wid < 16) ? 7 : 6;

    uint32_t aBase[7], bBase[7];
    int ldmask = 0;
    {
        int prev_tr = -1;
        #pragma unroll
        for (int s = 0; s < 7; ++s) {
            const int j = lo + s;
            const int pk = TRTAB[(j < 136) ? j : 135];
            const int tr = pk >> 4, tc = pk & 15;
            aBase[s] = sb + SM_HH
                + (uint32_t)(tr * 16 + (lane & 7) + (((lane >> 3) & 1) * 8)) * SRSB
                + (uint32_t)((lane >> 4) * 8) * 2;
            bBase[s] = sb + SM_HH
                + (uint32_t)(tc * 16 + (lane & 7) + ((lane >> 4) * 8)) * SRSB
                + (uint32_t)((lane >> 3) & 1) * 16;
            if (s < len && tr != prev_tr) ldmask |= 1 << s;
            if (s < len) prev_tr = tr;
        }
    }

    float et[56];
    #pragma unroll
    for (int i = 0; i < 56; ++i) et[i] = 0.f;

    // ---- phase 1 MMA: k-outer, slots inner, A reloaded only on tr change ----
    for (int k = 0; k < 8; ++k) {
        uint32_t ah[4], al[4];
        const uint32_t ko = (uint32_t)k * 32;
        #pragma unroll
        for (int s = 0; s < 7; ++s) {
            if (s < len) {
                if ((ldmask >> s) & 1) {
                    LDSM4(ah, aBase[s] + ko);
                    LDSM4(al, aBase[s] + HLOFF + ko);
                }
                uint32_t bh[4], bl[4];
                LDSM4(bh, bBase[s] + ko);
                LDSM4(bl, bBase[s] + HLOFF + ko);
                float* e = &et[8 * s];
                MMA16816(e,     ah, bh[0], bh[1]);
                MMA16816(e + 4, ah, bh[2], bh[3]);
                MMA16816(e,     al, bh[0], bh[1]);
                MMA16816(e + 4, al, bh[2], bh[3]);
                MMA16816(e,     ah, bl[0], bl[1]);
                MMA16816(e + 4, ah, bl[2], bl[3]);
            }
        }
    }

    // ---- phase 1 epilogue: exp + wsum contributions (rows direct, cols mirror) ----
    #pragma unroll
    for (int s = 0; s < 7; ++s) {
        if (s < len) {
            const int pk = TRTAB[lo + s];
            const int tr = pk >> 4, tc = pk & 15;
            float* e = &et[8 * s];

            const int r0 = tr * 16 + (lane >> 2), r1 = r0 + 8;
            const int c0 = tc * 16 + (lane & 3) * 2;
            const float ir0 = invv[r0], ir1 = invv[r1];
            const float ic0 = invv[c0], ic1 = invv[c0 + 1];
            const float ic8 = invv[c0 + 8], ic9 = invv[c0 + 9];
            e[0] = __expf(e[0] * ir0 * ic0); e[1] = __expf(e[1] * ir0 * ic1);
            e[2] = __expf(e[2] * ir1 * ic0); e[3] = __expf(e[3] * ir1 * ic1);
            e[4] = __expf(e[4] * ir0 * ic8); e[5] = __expf(e[5] * ir0 * ic9);
            e[6] = __expf(e[6] * ir1 * ic8); e[7] = __expf(e[7] * ir1 * ic9);

            // direct: ws[r] += sum_c e*m_c
            const float mc0 = mz[c0], mc1 = mz[c0 + 1], mc8 = mz[c0 + 8], mc9 = mz[c0 + 9];
            float rs0 = e[0] * mc0 + e[1] * mc1 + e[4] * mc8 + e[5] * mc9;
            float rs1 = e[2] * mc0 + e[3] * mc1 + e[6] * mc8 + e[7] * mc9;
            BFLY(rs0, 1); BFLY(rs0, 2);
            BFLY(rs1, 1); BFLY(rs1, 2);
            if ((lane & 3) == 0) {
                wsp[wid * 256 + r0] += rs0;
                wsp[wid * 256 + r1] += rs1;
            }
            // mirror: ws[c] += sum_r e*m_r  (skip on diagonal tiles)
            if (tr != tc) {
                const float mr0 = mz[r0], mr1 = mz[r1];
                float cs0 = e[0] * mr0 + e[2] * mr1;
                float cs1 = e[1] * mr0 + e[3] * mr1;
                float cs8 = e[4] * mr0 + e[6] * mr1;
                float cs9 = e[5] * mr0 + e[7] * mr1;
                BFLY(cs0, 4); BFLY(cs0, 8); BFLY(cs0, 16);
                BFLY(cs1, 4); BFLY(cs1, 8); BFLY(cs1, 16);
                BFLY(cs8, 4); BFLY(cs8, 8); BFLY(cs8, 16);
                BFLY(cs9, 4); BFLY(cs9, 8); BFLY(cs9, 16);
                if (lane < 4) {
                    const int cb = tc * 16 + lane * 2;
                    wsp[wid * 256 + cb]     += cs0;
                    wsp[wid * 256 + cb + 1] += cs1;
                    wsp[wid * 256 + cb + 8] += cs8;
                    wsp[wid * 256 + cb + 9] += cs9;
                }
            }
        }
    }
    __syncthreads();

    // ---- a_i = sel_i / wsum_i ----
    if (tid < 256) {
        float ws = 0.f;
        #pragma unroll
        for (int w = 0; w < NW; ++w) ws += wsp[w * 256 + tid];
        av[tid] = selv[tid] / ws;
    }
    __syncthreads();

    // ---- phase 2: v contributions from cached et (cols direct, rows mirror) ----
    #pragma unroll
    for (int s = 0; s < 7; ++s) {
        if (s < len) {
            const int pk = TRTAB[lo + s];
            const int tr = pk >> 4, tc = pk & 15;
            const float* e = &et[8 * s];
            const int r0 = tr * 16 + (lane >> 2), r1 = r0 + 8;
            const int c0 = tc * 16 + (lane & 3) * 2;

            // direct: v[c] += m_c * sum_r a_r e_rc
            const float ar0 = av[r0], ar1 = av[r1];
            float pc0 = ar0 * e[0] + ar1 * e[2];
            float pc1 = ar0 * e[1] + ar1 * e[3];
            float pc8 = ar0 * e[4] + ar1 * e[6];
            float pc9 = ar0 * e[5] + ar1 * e[7];
            BFLY(pc0, 4); BFLY(pc0, 8); BFLY(pc0, 16);
            BFLY(pc1, 4); BFLY(pc1, 8); BFLY(pc1, 16);
            BFLY(pc8, 4); BFLY(pc8, 8); BFLY(pc8, 16);
            BFLY(pc9, 4); BFLY(pc9, 8); BFLY(pc9, 16);
            if (lane < 4) {
                const int cb = tc * 16 + lane * 2;
                vpt[wid * 256 + cb]     += pc0 * mz[cb];
                vpt[wid * 256 + cb + 1] += pc1 * mz[cb + 1];
                vpt[wid * 256 + cb + 8] += pc8 * mz[cb + 8];
                vpt[wid * 256 + cb + 9] += pc9 * mz[cb + 9];
            }
            // mirror: v[r] += m_r * sum_c a_c e_rc  (skip on diagonal tiles)
            if (tr != tc) {
                const float ac0 = av[c0], ac1 = av[c0 + 1];
                const float ac8 = av[c0 + 8], ac9 = av[c0 + 9];
                float qr0 = ac0 * e[0] + ac1 * e[1] + ac8 * e[4] + ac9 * e[5];
                float qr1 = ac0 * e[2] + ac1 * e[3] + ac8 * e[6] + ac9 * e[7];
                BFLY(qr0, 1); BFLY(qr0, 2);
                BFLY(qr1, 1); BFLY(qr1, 2);
                if ((lane & 3) == 0) {
                    vpt[wid * 256 + r0] += qr0 * mz[r0];
                    vpt[wid * 256 + r1] += qr1 * mz[r1];
                }
            }
        }
    }
    __syncthreads();

    // ---- v = sum of warp partials ----
    if (tid < 256) {
        float v = 0.f;
        #pragma unroll
        for (int w = 0; w < NW; ++w) v += vpt[w * 256 + tid];
        vpt[tid] = v;   // own slot only: no race
    }
    __syncthreads();

    // ---- acc[d] = sum_j v_j * (Hh[j,d] + Hl[j,d]), 4-way split over j ----
    if (tid < 512) {
        const int d = tid & 127, jb = (tid >> 7) * 64;
        float a = 0.f;
        #pragma unroll 4
        for (int jx = 0; jx < 64; ++jx) {
            const int j = jb + jx;
            const float vj = vpt[j];
            const uint32_t off = (uint32_t)j * SRSB + (uint32_t)d * 2;
            float hv = __bfloat162float(*(__nv_bfloat16*)(smc + SM_HH + off))
                     + __bfloat162float(*(__nv_bfloat16*)(smc + SM_HL + off));
            a += vj * hv;
        }
        smf[SM_ACC / 4 + tid] = a;
    }
    __syncthreads();
    if (tid < D_) {   // h_last -> CX_HL (H region dead after the sync above)
        float s = smf[SM_ACC / 4 + tid] + smf[SM_ACC / 4 + 128 + tid]
                + smf[SM_ACC / 4 + 256 + tid] + smf[SM_ACC / 4 + 384 + tid];
        #pragma unroll
        for (int w = 0; w < NW; ++w) s += smf[SM_DP / 4 + w * D_ + tid];
        smf[CX_HL / 4 + tid] = s;
    }
    __syncthreads();

    // ---- cross cosine-attention over hist_2 + relu(h @ W) ----
    if (tid < 32) {
        float s = 0.f;
        #pragma unroll
        for (int c = 0; c < 4; ++c) { float v = smf[CX_HL / 4 + tid + 32 * c]; s += v * v; }
        #pragma unroll
        for (int o = 16; o; o >>= 1) s += __shfl_xor_sync(0xffffffffu, s, o);
        if (tid == 0) smf[CX_IQ / 4] = rsqrtf(s + EPSF);
    }
    __syncthreads();
    {
        const float invq = smf[CX_IQ / 4];
        const float* H2 = h2 + (size_t)b * 256 * D_;
        const float q0 = smf[CX_HL / 4 + lane * 4],     q1 = smf[CX_HL / 4 + lane * 4 + 1];
        const float q2 = smf[CX_HL / 4 + lane * 4 + 2], q3 = smf[CX_HL / 4 + lane * 4 + 3];
        float a0 = 0.f, a1 = 0.f, a2 = 0.f, a3 = 0.f, wp = 0.f;
        for (int k = wid; k < 256; k += NW) {
            float4 v = ((const float4*)(H2 + k * D_))[lane];
            float dot = v.x * q0 + v.y * q1 + v.z * q2 + v.w * q3;
            float nk  = v.x * v.x + v.y * v.y + v.z * v.z + v.w * v.w;
            #pragma unroll
            for (int o = 16; o; o >>= 1) {
                dot += __shfl_xor_sync(0xffffffffu, dot, o);
                nk  += __shfl_xor_sync(0xffffffffu, nk,  o);
            }
            float w = __expf(dot * rsqrtf(nk + EPSF) * invq)
                    * ((seq1[b * 256 + k] != 0) ? 1.f : 0.f);
            wp += w;
            a0 += w * v.x; a1 += w * v.y; a2 += w * v.z; a3 += w * v.w;
        }
        if (lane == 0) smf[CX_WS / 4 + wid] = wp;
        smf[CX_HA / 4 + wid * D_ + lane * 4]     = a0;
        smf[CX_HA / 4 + wid * D_ + lane * 4 + 1] = a1;
        smf[CX_HA / 4 + wid * D_ + lane * 4 + 2] = a2;
        smf[CX_HA / 4 + wid * D_ + lane * 4 + 3] = a3;
    }
    __syncthreads();
    if (tid < D_) {
        float ws = 0.f, s = 0.f;
        #pragma unroll
        for (int w = 0; w < NW; ++w) { ws += smf[CX_WS / 4 + w]; s += smf[CX_HA / 4 + w * D_ + tid]; }
        smf[CX_HV / 4 + tid] = s / ws;
    }
    __syncthreads();

    // ---- out = relu(hv @ W), 4-way split over d then combine ----
    if (tid < 512) {
        const int col = tid & 127, q = tid >> 7;
        float o = 0.f;
        #pragma unroll 8
        for (int dx = 0; dx < 32; ++dx) {
            const int d = q * 32 + dx;
            o += smf[CX_HV / 4 + d] * W[d * D_ + col];
        }
        smf[CX_HA / 4 + q * D_ + col] = o;   // reuse CX_HA (dead after hv combine)
    }
    __syncthreads();
    if (tid < D_) {
        float o = smf[CX_HA / 4 + tid] + smf[CX_HA / 4 + 128 + tid]
                + smf[CX_HA / 4 + 256 + tid] + smf[CX_HA / 4 + 384 + tid];
        out[b * D_ + tid] = fmaxf(o, 0.f);
    }
}

extern "C" void kernel_launch(void* const* d_in, const int* in_sizes, int n_in,
                              void* d_out, int out_size)
{
    const int*   seq  = (const int*)d_in[0];
    const int*   last = (const int*)d_in[1];
    const int*   seq1 = (const int*)d_in[2];
    const float* h1   = (const float*)d_in[3];
    const float* h2   = (const float*)d_in[4];
    const float* W    = (const float*)d_in[5];
    float* out = (float*)d_out;

    cudaFuncSetAttribute(fused_itd, cudaFuncAttributeMaxDynamicSharedMemorySize, SM_TOT);
    fused_itd<<<B_, NT, SM_TOT>>>(seq, last, seq1, h1, h2, W, out);
}

// round 14
// speedup vs baseline: 1.2967x; 1.0477x over previous
#include <cuda_runtime.h>
#include <cuda_bf16.h>
#include <cstdint>

#define B_   512
#define L_   256
#define D_   128
#define EPSF 0.01f
#define NW   24             // warps per CTA
#define NT   768            // threads per CTA
#define SRSB 272            // bf16 row stride in bytes: ldmatrix conflict-free
#define HLOFF 69632         // byte offset from HH to HL

// ---- smem byte offsets ----
#define SM_HH   0           // 256 x SRSB bf16 high split
#define SM_HL   69632       // low split
#define SM_INV  139264      // 256 f32
#define SM_M    140288      // 256 f32 key mask
#define SM_SEL  141312      // 256 f32 (mask*last)
#define SM_A    142336      // 256 f32 a_i = sel_i / wsum_i
#define SM_WSP  143360      // 24 x 256 f32 per-warp wsum partials
#define SM_VPT  167936      // 24 x 256 f32 per-warp v partials
#define SM_DP   192512      // 24 x 128 f32 direct-term partials
#define SM_ACC  204800      // 512 f32
#define SM_TOT  206848
// cross-phase aliases (H region dead by then)
#define CX_HL   0           // 128 f32
#define CX_WS   512         // 24 f32
#define CX_HA   1024        // 24 x 128 f32
#define CX_HV   13312       // 128 f32
#define CX_IQ   13824       // 1 f32

// packed (tr<<4 | tc) for upper-triangular job index j in [0,136)
__device__ __constant__ unsigned char TRTAB[136] = {
    0x00,0x01,0x02,0x03,0x04,0x05,0x06,0x07,0x08,0x09,0x0A,0x0B,0x0C,0x0D,0x0E,0x0F,
    0x11,0x12,0x13,0x14,0x15,0x16,0x17,0x18,0x19,0x1A,0x1B,0x1C,0x1D,0x1E,0x1F,
    0x22,0x23,0x24,0x25,0x26,0x27,0x28,0x29,0x2A,0x2B,0x2C,0x2D,0x2E,0x2F,
    0x33,0x34,0x35,0x36,0x37,0x38,0x39,0x3A,0x3B,0x3C,0x3D,0x3E,0x3F,
    0x44,0x45,0x46,0x47,0x48,0x49,0x4A,0x4B,0x4C,0x4D,0x4E,0x4F,
    0x55,0x56,0x57,0x58,0x59,0x5A,0x5B,0x5C,0x5D,0x5E,0x5F,
    0x66,0x67,0x68,0x69,0x6A,0x6B,0x6C,0x6D,0x6E,0x6F,
    0x77,0x78,0x79,0x7A,0x7B,0x7C,0x7D,0x7E,0x7F,
    0x88,0x89,0x8A,0x8B,0x8C,0x8D,0x8E,0x8F,
    0x99,0x9A,0x9B,0x9C,0x9D,0x9E,0x9F,
    0xAA,0xAB,0xAC,0xAD,0xAE,0xAF,
    0xBB,0xBC,0xBD,0xBE,0xBF,
    0xCC,0xCD,0xCE,0xCF,
    0xDD,0xDE,0xDF,
    0xEE,0xEF,
    0xFF
};

__device__ __forceinline__ uint32_t smem_u32(const void* p) {
    uint32_t a;
    asm("{ .reg .u64 t; cvta.to.shared.u64 t, %1; cvt.u32.u64 %0, t; }" : "=r"(a) : "l"(p));
    return a;
}
#define LDSM4(r, addr) \
    asm volatile("ldmatrix.sync.aligned.m8n8.x4.shared.b16 {%0,%1,%2,%3}, [%4];" \
        : "=r"((r)[0]), "=r"((r)[1]), "=r"((r)[2]), "=r"((r)[3]) : "r"(addr))
#define MMA16816(c, a, b0, b1) \
    asm volatile("mma.sync.aligned.m16n8k16.row.col.f32.bf16.bf16.f32 " \
        "{%0,%1,%2,%3}, {%4,%5,%6,%7}, {%8,%9}, {%0,%1,%2,%3};" \
        : "+f"((c)[0]), "+f"((c)[1]), "+f"((c)[2]), "+f"((c)[3]) \
        : "r"((a)[0]), "r"((a)[1]), "r"((a)[2]), "r"((a)[3]), "r"(b0), "r"(b1))
#define BFLY(x, o) x += __shfl_xor_sync(0xffffffffu, x, o)

// bf16 round trip kept as bit ops (bf16<->f32 is a 16-bit shift)
__device__ __forceinline__ uint32_t bfbits(float x) {
    return (uint32_t)__nv_bfloat16_raw(__float2bfloat16_rn(x)).x;
}
__device__ __forceinline__ float bflo(uint32_t p) { return __uint_as_float(p << 16); }
__device__ __forceinline__ float bfhi(uint32_t p) { return __uint_as_float(p & 0xFFFF0000u); }

__global__ __launch_bounds__(NT, 1)
void fused_itd(const int* __restrict__ seq, const int* __restrict__ last,
               const int* __restrict__ seq1, const float* __restrict__ h1,
               const float* __restrict__ h2, const float* __restrict__ W,
               float* __restrict__ out)
{
    extern __shared__ unsigned char smraw[];
    float* smf = (float*)smraw;
    unsigned char* smc = smraw;
    const uint32_t sb = smem_u32(smraw);
    const int b = blockIdx.x, tid = threadIdx.x, wid = tid >> 5, lane = tid & 31;

    float* invv = smf + SM_INV / 4;
    float* mz   = smf + SM_M / 4;
    float* selv = smf + SM_SEL / 4;
    float* av   = smf + SM_A / 4;
    float* wsp  = smf + SM_WSP / 4;
    float* vpt  = smf + SM_VPT / 4;

    // ---- masks / zero-init of partial arrays ----
    if (tid < 256) {
        int sv = seq[b * L_ + tid], lv = last[b * L_ + tid];
        float m = (sv != 0) ? 1.f : 0.f;
        mz[tid]   = m;
        selv[tid] = m * (float)lv;
    }
    for (int i = tid; i < 2 * NW * 256; i += NT) wsp[i] = 0.f;   // wsp + vpt contiguous
    __syncthreads();

    // ---- load hist_1[b]: split to bf16 hi/lo, norms, direct sel*h term ----
    const float4* src4 = (const float4*)(h1 + (size_t)b * L_ * D_);
    const int d0 = lane * 4;
    float ds0 = 0.f, ds1 = 0.f, ds2 = 0.f, ds3 = 0.f;
    for (int i = wid; i < 256; i += NW) {
        const float4 v = src4[i * 32 + lane];
        float np = v.x * v.x + v.y * v.y + v.z * v.z + v.w * v.w;
        #pragma unroll
        for (int o = 16; o; o >>= 1) np += __shfl_xor_sync(0xffffffffu, np, o);
        if (lane == 0) invv[i] = rsqrtf(np + EPSF);
        const float se = selv[i];
        ds0 += se * v.x; ds1 += se * v.y; ds2 += se * v.z; ds3 += se * v.w;

        float xs[4] = { v.x, v.y, v.z, v.w };
        uint16_t hh[4], hl[4];
        #pragma unroll
        for (int j = 0; j < 4; ++j) {
            __nv_bfloat16 hb = __float2bfloat16_rn(xs[j]);
            __nv_bfloat16 lb = __float2bfloat16_rn(xs[j] - __bfloat162float(hb));
            hh[j] = __nv_bfloat16_raw(hb).x;
            hl[j] = __nv_bfloat16_raw(lb).x;
        }
        uint32_t off = (uint32_t)i * SRSB + (uint32_t)d0 * 2;
        *(uint2*)(smc + SM_HH + off) = make_uint2(
            (uint32_t)hh[0] | ((uint32_t)hh[1] << 16), (uint32_t)hh[2] | ((uint32_t)hh[3] << 16));
        *(uint2*)(smc + SM_HL + off) = make_uint2(
            (uint32_t)hl[0] | ((uint32_t)hl[1] << 16), (uint32_t)hl[2] | ((uint32_t)hl[3] << 16));
    }
    smf[SM_DP / 4 + wid * D_ + d0 + 0] = ds0;
    smf[SM_DP / 4 + wid * D_ + d0 + 1] = ds1;
    smf[SM_DP / 4 + wid * D_ + d0 + 2] = ds2;
    smf[SM_DP / 4 + wid * D_ + d0 + 3] = ds3;
    __syncthreads();

    // =======================================================================
    // Self attention on upper-triangular 16x16 tiles (136 jobs, 24 warps).
    // Warp w owns a CONTIGUOUS run of 6 (w<16) or 5 tiles, processed in two
    // groups of <=3 (A-fragment reuse inside a group). e-tiles are rounded
    // to bf16 and cached PACKED in registers across the wsum barrier; wsum
    // uses the rounded values so normalization stays consistent.
    // =======================================================================
    const int lo  = (wid < 16) ? wid * 6 : 96 + (wid - 16) * 5;
    const int len = (wid < 16) ? 6 : 5;

    uint32_t etp[24];   // 6 tiles x 4 bf16x2 regs

    // ---- phase 1: two groups of <=3 tiles ----
    #pragma unroll
    for (int g = 0; g < 2; ++g) {
        const int gb  = lo + 3 * g;
        const int cnt = len - 3 * g;            // 3 or 2

        uint32_t aB[3], bB[3];
        int ldm = 0;
        {
            int prev_tr = -1;
            #pragma unroll
            for (int s = 0; s < 3; ++s) {
                const int j = gb + s;
                const int pk = TRTAB[(j < 136) ? j : 135];
                const int tr = pk >> 4, tc = pk & 15;
                aB[s] = sb + SM_HH
                    + (uint32_t)(tr * 16 + (lane & 7) + (((lane >> 3) & 1) * 8)) * SRSB
                    + (uint32_t)((lane >> 4) * 8) * 2;
                bB[s] = sb + SM_HH
                    + (uint32_t)(tc * 16 + (lane & 7) + ((lane >> 4) * 8)) * SRSB
                    + (uint32_t)((lane >> 3) & 1) * 16;
                if (s < cnt && tr != prev_tr) ldm |= 1 << s;
                if (s < cnt) prev_tr = tr;
            }
        }

        float acc[24];
        #pragma unroll
        for (int i = 0; i < 24; ++i) acc[i] = 0.f;

        for (int k = 0; k < 8; ++k) {
            uint32_t ah[4], al[4];
            const uint32_t ko = (uint32_t)k * 32;
            #pragma unroll
            for (int s = 0; s < 3; ++s) {
                if (s < cnt) {
                    if ((ldm >> s) & 1) {
                        LDSM4(ah, aB[s] + ko);
                        LDSM4(al, aB[s] + HLOFF + ko);
                    }
                    uint32_t bh[4], bl[4];
                    LDSM4(bh, bB[s] + ko);
                    LDSM4(bl, bB[s] + HLOFF + ko);
                    float* e = &acc[8 * s];
                    MMA16816(e,     ah, bh[0], bh[1]);
                    MMA16816(e + 4, ah, bh[2], bh[3]);
                    MMA16816(e,     al, bh[0], bh[1]);
                    MMA16816(e + 4, al, bh[2], bh[3]);
                    MMA16816(e,     ah, bl[0], bl[1]);
                    MMA16816(e + 4, ah, bl[2], bl[3]);
                }
            }
        }

        // group epilogue: exp -> bf16 round -> pack + wsum contributions
        #pragma unroll
        for (int s = 0; s < 3; ++s) {
            if (s < cnt) {
                const int pk = TRTAB[gb + s];
                const int tr = pk >> 4, tc = pk & 15;
                float* a = &acc[8 * s];

                const int r0 = tr * 16 + (lane >> 2), r1 = r0 + 8;
                const int c0 = tc * 16 + (lane & 3) * 2;
                const float ir0 = invv[r0], ir1 = invv[r1];
                const float ic0 = invv[c0], ic1 = invv[c0 + 1];
                const float ic8 = invv[c0 + 8], ic9 = invv[c0 + 9];

                float e[8];
                uint32_t bits[8];
                e[0] = __expf(a[0] * ir0 * ic0); e[1] = __expf(a[1] * ir0 * ic1);
                e[2] = __expf(a[2] * ir1 * ic0); e[3] = __expf(a[3] * ir1 * ic1);
                e[4] = __expf(a[4] * ir0 * ic8); e[5] = __expf(a[5] * ir0 * ic9);
                e[6] = __expf(a[6] * ir1 * ic8); e[7] = __expf(a[7] * ir1 * ic9);
                #pragma unroll
                for (int i = 0; i < 8; ++i) { bits[i] = bfbits(e[i]); e[i] = __uint_as_float(bits[i] << 16); }
                const int ti = (gb + s) - lo;   // 0..5
                etp[4 * ti + 0] = bits[0] | (bits[1] << 16);
                etp[4 * ti + 1] = bits[2] | (bits[3] << 16);
                etp[4 * ti + 2] = bits[4] | (bits[5] << 16);
                etp[4 * ti + 3] = bits[6] | (bits[7] << 16);

                // direct: ws[r] += sum_c e*m_c
                const float mc0 = mz[c0], mc1 = mz[c0 + 1], mc8 = mz[c0 + 8], mc9 = mz[c0 + 9];
                float rs0 = e[0] * mc0 + e[1] * mc1 + e[4] * mc8 + e[5] * mc9;
                float rs1 = e[2] * mc0 + e[3] * mc1 + e[6] * mc8 + e[7] * mc9;
                BFLY(rs0, 1); BFLY(rs0, 2);
                BFLY(rs1, 1); BFLY(rs1, 2);
                if ((lane & 3) == 0) {
                    wsp[wid * 256 + r0] += rs0;
                    wsp[wid * 256 + r1] += rs1;
                }
                // mirror: ws[c] += sum_r e*m_r  (skip on diagonal tiles)
                if (tr != tc) {
                    const float mr0 = mz[r0], mr1 = mz[r1];
                    float cs0 = e[0] * mr0 + e[2] * mr1;
                    float cs1 = e[1] * mr0 + e[3] * mr1;
                    float cs8 = e[4] * mr0 + e[6] * mr1;
                    float cs9 = e[5] * mr0 + e[7] * mr1;
                    BFLY(cs0, 4); BFLY(cs0, 8); BFLY(cs0, 16);
                    BFLY(cs1, 4); BFLY(cs1, 8); BFLY(cs1, 16);
                    BFLY(cs8, 4); BFLY(cs8, 8); BFLY(cs8, 16);
                    BFLY(cs9, 4); BFLY(cs9, 8); BFLY(cs9, 16);
                    if (lane < 4) {
                        const int cb = tc * 16 + lane * 2;
                        wsp[wid * 256 + cb]     += cs0;
                        wsp[wid * 256 + cb + 1] += cs1;
                        wsp[wid * 256 + cb + 8] += cs8;
                        wsp[wid * 256 + cb + 9] += cs9;
                    }
                }
            }
        }
    }
    __syncthreads();

    // ---- a_i = sel_i / wsum_i ----
    if (tid < 256) {
        float ws = 0.f;
        #pragma unroll
        for (int w = 0; w < NW; ++w) ws += wsp[w * 256 + tid];
        av[tid] = selv[tid] / ws;
    }
    __syncthreads();

    // ---- phase 2: v contributions from packed et (cols direct, rows mirror) ----
    #pragma unroll
    for (int s = 0; s < 6; ++s) {
        if (s < len) {
            const int pk = TRTAB[lo + s];
            const int tr = pk >> 4, tc = pk & 15;
            float e[8];
            e[0] = bflo(etp[4 * s + 0]); e[1] = bfhi(etp[4 * s + 0]);
            e[2] = bflo(etp[4 * s + 1]); e[3] = bfhi(etp[4 * s + 1]);
            e[4] = bflo(etp[4 * s + 2]); e[5] = bfhi(etp[4 * s + 2]);
            e[6] = bflo(etp[4 * s + 3]); e[7] = bfhi(etp[4 * s + 3]);
            const int r0 = tr * 16 + (lane >> 2), r1 = r0 + 8;
            const int c0 = tc * 16 + (lane & 3) * 2;

            // direct: v[c] += m_c * sum_r a_r e_rc
            const float ar0 = av[r0], ar1 = av[r1];
            float pc0 = ar0 * e[0] + ar1 * e[2];
            float pc1 = ar0 * e[1] + ar1 * e[3];
            float pc8 = ar0 * e[4] + ar1 * e[6];
            float pc9 = ar0 * e[5] + ar1 * e[7];
            BFLY(pc0, 4); BFLY(pc0, 8); BFLY(pc0, 16);
            BFLY(pc1, 4); BFLY(pc1, 8); BFLY(pc1, 16);
            BFLY(pc8, 4); BFLY(pc8, 8); BFLY(pc8, 16);
            BFLY(pc9, 4); BFLY(pc9, 8); BFLY(pc9, 16);
            if (lane < 4) {
                const int cb = tc * 16 + lane * 2;
                vpt[wid * 256 + cb]     += pc0 * mz[cb];
                vpt[wid * 256 + cb + 1] += pc1 * mz[cb + 1];
                vpt[wid * 256 + cb + 8] += pc8 * mz[cb + 8];
                vpt[wid * 256 + cb + 9] += pc9 * mz[cb + 9];
            }
            // mirror: v[r] += m_r * sum_c a_c e_rc  (skip on diagonal tiles)
            if (tr != tc) {
                const float ac0 = av[c0], ac1 = av[c0 + 1];
                const float ac8 = av[c0 + 8], ac9 = av[c0 + 9];
                float qr0 = ac0 * e[0] + ac1 * e[1] + ac8 * e[4] + ac9 * e[5];
                float qr1 = ac0 * e[2] + ac1 * e[3] + ac8 * e[6] + ac9 * e[7];
                BFLY(qr0, 1); BFLY(qr0, 2);
                BFLY(qr1, 1); BFLY(qr1, 2);
                if ((lane & 3) == 0) {
                    vpt[wid * 256 + r0] += qr0 * mz[r0];
                    vpt[wid * 256 + r1] += qr1 * mz[r1];
                }
            }
        }
    }
    __syncthreads();

    // ---- v = sum of warp partials ----
    if (tid < 256) {
        float v = 0.f;
        #pragma unroll
        for (int w = 0; w < NW; ++w) v += vpt[w * 256 + tid];
        vpt[tid] = v;   // own slot only: no race
    }
    __syncthreads();

    // ---- acc[d] = sum_j v_j * (Hh[j,d] + Hl[j,d]), 4-way split over j ----
    if (tid < 512) {
        const int d = tid & 127, jb = (tid >> 7) * 64;
        float a = 0.f;
        #pragma unroll 4
        for (int jx = 0; jx < 64; ++jx) {
            const int j = jb + jx;
            const float vj = vpt[j];
            const uint32_t off = (uint32_t)j * SRSB + (uint32_t)d * 2;
            float hv = __bfloat162float(*(__nv_bfloat16*)(smc + SM_HH + off))
                     + __bfloat162float(*(__nv_bfloat16*)(smc + SM_HL + off));
            a += vj * hv;
        }
        smf[SM_ACC / 4 + tid] = a;
    }
    __syncthreads();
    if (tid < D_) {   // h_last -> CX_HL (H region dead after the sync above)
        float s = smf[SM_ACC / 4 + tid] + smf[SM_ACC / 4 + 128 + tid]
                + smf[SM_ACC / 4 + 256 + tid] + smf[SM_ACC / 4 + 384 + tid];
        #pragma unroll
        for (int w = 0; w < NW; ++w) s += smf[SM_DP / 4 + w * D_ + tid];
        smf[CX_HL / 4 + tid] = s;
    }
    __syncthreads();

    // ---- cross cosine-attention over hist_2 + relu(h @ W) ----
    if (tid < 32) {
        float s = 0.f;
        #pragma unroll
        for (int c = 0; c < 4; ++c) { float v = smf[CX_HL / 4 + tid + 32 * c]; s += v * v; }
        #pragma unroll
        for (int o = 16; o; o >>= 1) s += __shfl_xor_sync(0xffffffffu, s, o);
        if (tid == 0) smf[CX_IQ / 4] = rsqrtf(s + EPSF);
    }
    __syncthreads();
    {
        const float invq = smf[CX_IQ / 4];
        const float* H2 = h2 + (size_t)b * 256 * D_;
        const float q0 = smf[CX_HL / 4 + lane * 4],     q1 = smf[CX_HL / 4 + lane * 4 + 1];
        const float q2 = smf[CX_HL / 4 + lane * 4 + 2], q3 = smf[CX_HL / 4 + lane * 4 + 3];
        float a0 = 0.f, a1 = 0.f, a2 = 0.f, a3 = 0.f, wp = 0.f;
        for (int k = wid; k < 256; k += NW) {
            float4 v = ((const float4*)(H2 + k * D_))[lane];
            float dot = v.x * q0 + v.y * q1 + v.z * q2 + v.w * q3;
            float nk  = v.x * v.x + v.y * v.y + v.z * v.z + v.w * v.w;
            #pragma unroll
            for (int o = 16; o; o >>= 1) {
                dot += __shfl_xor_sync(0xffffffffu, dot, o);
                nk  += __shfl_xor_sync(0xffffffffu, nk,  o);
            }
            float w = __expf(dot * rsqrtf(nk + EPSF) * invq)
                    * ((seq1[b * 256 + k] != 0) ? 1.f : 0.f);
            wp += w;
            a0 += w * v.x; a1 += w * v.y; a2 += w * v.z; a3 += w * v.w;
        }
        if (lane == 0) smf[CX_WS / 4 + wid] = wp;
        smf[CX_HA / 4 + wid * D_ + lane * 4]     = a0;
        smf[CX_HA / 4 + wid * D_ + lane * 4 + 1] = a1;
        smf[CX_HA / 4 + wid * D_ + lane * 4 + 2] = a2;
        smf[CX_HA / 4 + wid * D_ + lane * 4 + 3] = a3;
    }
    __syncthreads();
    if (tid < D_) {
        float ws = 0.f, s = 0.f;
        #pragma unroll
        for (int w = 0; w < NW; ++w) { ws += smf[CX_WS / 4 + w]; s += smf[CX_HA / 4 + w * D_ + tid]; }
        smf[CX_HV / 4 + tid] = s / ws;
    }
    __syncthreads();

    // ---- out = relu(hv @ W), 4-way split over d then combine ----
    if (tid < 512) {
        const int col = tid & 127, q = tid >> 7;
        float o = 0.f;
        #pragma unroll 8
        for (int dx = 0; dx < 32; ++dx) {
            const int d = q * 32 + dx;
            o += smf[CX_HV / 4 + d] * W[d * D_ + col];
        }
        smf[CX_HA / 4 + q * D_ + col] = o;   // reuse CX_HA (dead after hv combine)
    }
    __syncthreads();
    if (tid < D_) {
        float o = smf[CX_HA / 4 + tid] + smf[CX_HA / 4 + 128 + tid]
                + smf[CX_HA / 4 + 256 + tid] + smf[CX_HA / 4 + 384 + tid];
        out[b * D_ + tid] = fmaxf(o, 0.f);
    }
}

extern "C" void kernel_launch(void* const* d_in, const int* in_sizes, int n_in,
                              void* d_out, int out_size)
{
    const int*   seq  = (const int*)d_in[0];
    const int*   last = (const int*)d_in[1];
    const int*   seq1 = (const int*)d_in[2];
    const float* h1   = (const float*)d_in[3];
    const float* h2   = (const float*)d_in[4];
    const float* W    = (const float*)d_in[5];
    float* out = (float*)d_out;

    cudaFuncSetAttribute(fused_itd, cudaFuncAttributeMaxDynamicSharedMemorySize, SM_TOT);
    fused_itd<<<B_, NT, SM_TOT>>>(seq, last, seq1, h1, h2, W, out);
}

// round 15
// speedup vs baseline: 1.5182x; 1.1708x over previous
#include <cuda_runtime.h>
#include <cuda_bf16.h>
#include <cstdint>

#define B_   512
#define L_   256
#define D_   128
#define EPSF 0.01f
#define NW   24             // warps per CTA
#define NT   768            // threads per CTA
#define SRSB 272            // bf16 row stride in bytes: ldmatrix conflict-free

// ---- smem byte offsets ----
#define SM_HN   0           // 256 x SRSB bf16 normalized rows
#define SM_NRM  69632       // 256 f32  ||h||   (sqrt(np+eps))
#define SM_M    70656       // 256 f32 key mask
#define SM_SEL  71680       // 256 f32 (mask*last)
#define SM_A    72704       // 256 f32 a_i = sel_i / wsum_i
#define SM_WSP  73728       // 24 x 256 f32 per-warp wsum partials
#define SM_VPT  98304       // 24 x 256 f32 per-warp v partials
#define SM_DP   122880      // 24 x 128 f32 direct-term partials
#define SM_ACC  135168      // 512 f32
#define SM_TOT  137216
// cross-phase aliases (Hn region dead by then)
#define CX_HL   0           // 128 f32
#define CX_WS   512         // 24 f32
#define CX_HA   1024        // 24 x 128 f32
#define CX_HV   13312       // 128 f32
#define CX_IQ   13824       // 1 f32

// packed (tr<<4 | tc) for upper-triangular job index j in [0,136)
__device__ __constant__ unsigned char TRTAB[136] = {
    0x00,0x01,0x02,0x03,0x04,0x05,0x06,0x07,0x08,0x09,0x0A,0x0B,0x0C,0x0D,0x0E,0x0F,
    0x11,0x12,0x13,0x14,0x15,0x16,0x17,0x18,0x19,0x1A,0x1B,0x1C,0x1D,0x1E,0x1F,
    0x22,0x23,0x24,0x25,0x26,0x27,0x28,0x29,0x2A,0x2B,0x2C,0x2D,0x2E,0x2F,
    0x33,0x34,0x35,0x36,0x37,0x38,0x39,0x3A,0x3B,0x3C,0x3D,0x3E,0x3F,
    0x44,0x45,0x46,0x47,0x48,0x49,0x4A,0x4B,0x4C,0x4D,0x4E,0x4F,
    0x55,0x56,0x57,0x58,0x59,0x5A,0x5B,0x5C,0x5D,0x5E,0x5F,
    0x66,0x67,0x68,0x69,0x6A,0x6B,0x6C,0x6D,0x6E,0x6F,
    0x77,0x78,0x79,0x7A,0x7B,0x7C,0x7D,0x7E,0x7F,
    0x88,0x89,0x8A,0x8B,0x8C,0x8D,0x8E,0x8F,
    0x99,0x9A,0x9B,0x9C,0x9D,0x9E,0x9F,
    0xAA,0xAB,0xAC,0xAD,0xAE,0xAF,
    0xBB,0xBC,0xBD,0xBE,0xBF,
    0xCC,0xCD,0xCE,0xCF,
    0xDD,0xDE,0xDF,
    0xEE,0xEF,
    0xFF
};

__device__ __forceinline__ uint32_t smem_u32(const void* p) {
    uint32_t a;
    asm("{ .reg .u64 t; cvta.to.shared.u64 t, %1; cvt.u32.u64 %0, t; }" : "=r"(a) : "l"(p));
    return a;
}
#define LDSM4(r, addr) \
    asm volatile("ldmatrix.sync.aligned.m8n8.x4.shared.b16 {%0,%1,%2,%3}, [%4];" \
        : "=r"((r)[0]), "=r"((r)[1]), "=r"((r)[2]), "=r"((r)[3]) : "r"(addr))
#define MMA16816(c, a, b0, b1) \
    asm volatile("mma.sync.aligned.m16n8k16.row.col.f32.bf16.bf16.f32 " \
        "{%0,%1,%2,%3}, {%4,%5,%6,%7}, {%8,%9}, {%0,%1,%2,%3};" \
        : "+f"((c)[0]), "+f"((c)[1]), "+f"((c)[2]), "+f"((c)[3]) \
        : "r"((a)[0]), "r"((a)[1]), "r"((a)[2]), "r"((a)[3]), "r"(b0), "r"(b1))
#define BFLY(x, o) x += __shfl_xor_sync(0xffffffffu, x, o)

__device__ __forceinline__ uint16_t bf16b(float x) {
    return __nv_bfloat16_raw(__float2bfloat16_rn(x)).x;
}

__global__ __launch_bounds__(NT, 1)
void fused_itd(const int* __restrict__ seq, const int* __restrict__ last,
               const int* __restrict__ seq1, const float* __restrict__ h1,
               const float* __restrict__ h2, const float* __restrict__ W,
               float* __restrict__ out)
{
    extern __shared__ unsigned char smraw[];
    float* smf = (float*)smraw;
    unsigned char* smc = smraw;
    const uint32_t sb = smem_u32(smraw);
    const int b = blockIdx.x, tid = threadIdx.x, wid = tid >> 5, lane = tid & 31;

    float* nrm  = smf + SM_NRM / 4;
    float* mz   = smf + SM_M / 4;
    float* selv = smf + SM_SEL / 4;
    float* av   = smf + SM_A / 4;
    float* wsp  = smf + SM_WSP / 4;
    float* vpt  = smf + SM_VPT / 4;

    // ---- masks / zero-init of partial arrays ----
    if (tid < 256) {
        int sv = seq[b * L_ + tid], lv = last[b * L_ + tid];
        float m = (sv != 0) ? 1.f : 0.f;
        mz[tid]   = m;
        selv[tid] = m * (float)lv;
    }
    for (int i = tid; i < 2 * NW * 256; i += NT) wsp[i] = 0.f;   // wsp + vpt contiguous
    __syncthreads();

    // ---- load hist_1[b]: normalize rows -> bf16 Hn, keep ||h||, direct term ----
    const float4* src4 = (const float4*)(h1 + (size_t)b * L_ * D_);
    const int d0 = lane * 4;
    float ds0 = 0.f, ds1 = 0.f, ds2 = 0.f, ds3 = 0.f;
    for (int i = wid; i < 256; i += NW) {
        const float4 v = src4[i * 32 + lane];
        float np = v.x * v.x + v.y * v.y + v.z * v.z + v.w * v.w;
        #pragma unroll
        for (int o = 16; o; o >>= 1) np += __shfl_xor_sync(0xffffffffu, np, o);
        const float invf = rsqrtf(np + EPSF);
        if (lane == 0) nrm[i] = sqrtf(np + EPSF);
        const float se = selv[i];
        ds0 += se * v.x; ds1 += se * v.y; ds2 += se * v.z; ds3 += se * v.w;

        uint16_t hn0 = bf16b(v.x * invf), hn1 = bf16b(v.y * invf);
        uint16_t hn2 = bf16b(v.z * invf), hn3 = bf16b(v.w * invf);
        uint32_t off = (uint32_t)i * SRSB + (uint32_t)d0 * 2;
        *(uint2*)(smc + SM_HN + off) = make_uint2(
            (uint32_t)hn0 | ((uint32_t)hn1 << 16), (uint32_t)hn2 | ((uint32_t)hn3 << 16));
    }
    smf[SM_DP / 4 + wid * D_ + d0 + 0] = ds0;
    smf[SM_DP / 4 + wid * D_ + d0 + 1] = ds1;
    smf[SM_DP / 4 + wid * D_ + d0 + 2] = ds2;
    smf[SM_DP / 4 + wid * D_ + d0 + 3] = ds3;
    __syncthreads();

    // =======================================================================
    // Self attention on upper-triangular 16x16 tiles (136 jobs, 24 warps).
    // cos comes DIRECTLY from one bf16 MMA product of normalized rows.
    // Each warp owns <=6 contiguous tiles, A fragment reused on same tr.
    // e-tiles cached fp32 in registers across the wsum barrier.
    // =======================================================================
    const int lo  = (wid < 16) ? wid * 6 : 96 + (wid - 16) * 5;
    const int len = (wid < 16) ? 6 : 5;

    uint32_t aB[6], bB[6];
    int ldm = 0;
    {
        int prev_tr = -1;
        #pragma unroll
        for (int s = 0; s < 6; ++s) {
            const int j = lo + s;
            const int pk = TRTAB[(j < 136) ? j : 135];
            const int tr = pk >> 4, tc = pk & 15;
            aB[s] = sb + SM_HN
                + (uint32_t)(tr * 16 + (lane & 7) + (((lane >> 3) & 1) * 8)) * SRSB
                + (uint32_t)((lane >> 4) * 8) * 2;
            bB[s] = sb + SM_HN
                + (uint32_t)(tc * 16 + (lane & 7) + ((lane >> 4) * 8)) * SRSB
                + (uint32_t)((lane >> 3) & 1) * 16;
            if (s < len && tr != prev_tr) ldm |= 1 << s;
            if (s < len) prev_tr = tr;
        }
    }

    float et[48];
    #pragma unroll
    for (int i = 0; i < 48; ++i) et[i] = 0.f;

    // ---- phase 1 MMA: k-outer, slots inner, A reloaded only on tr change ----
    for (int k = 0; k < 8; ++k) {
        uint32_t ah[4];
        const uint32_t ko = (uint32_t)k * 32;
        #pragma unroll
        for (int s = 0; s < 6; ++s) {
            if (s < len) {
                if ((ldm >> s) & 1) LDSM4(ah, aB[s] + ko);
                uint32_t bh[4];
                LDSM4(bh, bB[s] + ko);
                float* e = &et[8 * s];
                MMA16816(e,     ah, bh[0], bh[1]);
                MMA16816(e + 4, ah, bh[2], bh[3]);
            }
        }
    }

    // ---- phase 1 epilogue: e = exp(cos) + wsum contributions ----
    #pragma unroll
    for (int s = 0; s < 6; ++s) {
        if (s < len) {
            const int pk = TRTAB[lo + s];
            const int tr = pk >> 4, tc = pk & 15;
            float* e = &et[8 * s];

            const int r0 = tr * 16 + (lane >> 2), r1 = r0 + 8;
            const int c0 = tc * 16 + (lane & 3) * 2;
            #pragma unroll
            for (int i = 0; i < 8; ++i) e[i] = __expf(e[i]);

            // direct: ws[r] += sum_c e*m_c
            const float mc0 = mz[c0], mc1 = mz[c0 + 1], mc8 = mz[c0 + 8], mc9 = mz[c0 + 9];
            float rs0 = e[0] * mc0 + e[1] * mc1 + e[4] * mc8 + e[5] * mc9;
            float rs1 = e[2] * mc0 + e[3] * mc1 + e[6] * mc8 + e[7] * mc9;
            BFLY(rs0, 1); BFLY(rs0, 2);
            BFLY(rs1, 1); BFLY(rs1, 2);
            if ((lane & 3) == 0) {
                wsp[wid * 256 + r0] += rs0;
                wsp[wid * 256 + r1] += rs1;
            }
            // mirror: ws[c] += sum_r e*m_r  (skip on diagonal tiles)
            if (tr != tc) {
                const float mr0 = mz[r0], mr1 = mz[r1];
                float cs0 = e[0] * mr0 + e[2] * mr1;
                float cs1 = e[1] * mr0 + e[3] * mr1;
                float cs8 = e[4] * mr0 + e[6] * mr1;
                float cs9 = e[5] * mr0 + e[7] * mr1;
                BFLY(cs0, 4); BFLY(cs0, 8); BFLY(cs0, 16);
                BFLY(cs1, 4); BFLY(cs1, 8); BFLY(cs1, 16);
                BFLY(cs8, 4); BFLY(cs8, 8); BFLY(cs8, 16);
                BFLY(cs9, 4); BFLY(cs9, 8); BFLY(cs9, 16);
                if (lane < 4) {
                    const int cb = tc * 16 + lane * 2;
                    wsp[wid * 256 + cb]     += cs0;
                    wsp[wid * 256 + cb + 1] += cs1;
                    wsp[wid * 256 + cb + 8] += cs8;
                    wsp[wid * 256 + cb + 9] += cs9;
                }
            }
        }
    }
    __syncthreads();

    // ---- a_i = sel_i / wsum_i ----
    if (tid < 256) {
        float ws = 0.f;
        #pragma unroll
        for (int w = 0; w < NW; ++w) ws += wsp[w * 256 + tid];
        av[tid] = selv[tid] / ws;
    }
    __syncthreads();

    // ---- phase 2: v contributions from cached et (cols direct, rows mirror) ----
    #pragma unroll
    for (int s = 0; s < 6; ++s) {
        if (s < len) {
            const int pk = TRTAB[lo + s];
            const int tr = pk >> 4, tc = pk & 15;
            const float* e = &et[8 * s];
            const int r0 = tr * 16 + (lane >> 2), r1 = r0 + 8;
            const int c0 = tc * 16 + (lane & 3) * 2;

            // direct: v[c] += m_c * sum_r a_r e_rc
            const float ar0 = av[r0], ar1 = av[r1];
            float pc0 = ar0 * e[0] + ar1 * e[2];
            float pc1 = ar0 * e[1] + ar1 * e[3];
            float pc8 = ar0 * e[4] + ar1 * e[6];
            float pc9 = ar0 * e[5] + ar1 * e[7];
            BFLY(pc0, 4); BFLY(pc0, 8); BFLY(pc0, 16);
            BFLY(pc1, 4); BFLY(pc1, 8); BFLY(pc1, 16);
            BFLY(pc8, 4); BFLY(pc8, 8); BFLY(pc8, 16);
            BFLY(pc9, 4); BFLY(pc9, 8); BFLY(pc9, 16);
            if (lane < 4) {
                const int cb = tc * 16 + lane * 2;
                vpt[wid * 256 + cb]     += pc0 * mz[cb];
                vpt[wid * 256 + cb + 1] += pc1 * mz[cb + 1];
                vpt[wid * 256 + cb + 8] += pc8 * mz[cb + 8];
                vpt[wid * 256 + cb + 9] += pc9 * mz[cb + 9];
            }
            // mirror: v[r] += m_r * sum_c a_c e_rc  (skip on diagonal tiles)
            if (tr != tc) {
                const float ac0 = av[c0], ac1 = av[c0 + 1];
                const float ac8 = av[c0 + 8], ac9 = av[c0 + 9];
                float qr0 = ac0 * e[0] + ac1 * e[1] + ac8 * e[4] + ac9 * e[5];
                float qr1 = ac0 * e[2] + ac1 * e[3] + ac8 * e[6] + ac9 * e[7];
                BFLY(qr0, 1); BFLY(qr0, 2);
                BFLY(qr1, 1); BFLY(qr1, 2);
                if ((lane & 3) == 0) {
                    vpt[wid * 256 + r0] += qr0 * mz[r0];
                    vpt[wid * 256 + r1] += qr1 * mz[r1];
                }
            }
        }
    }
    __syncthreads();

    // ---- v = sum of warp partials, rescaled by ||h_j|| (Hn -> h recovery) ----
    if (tid < 256) {
        float v = 0.f;
        #pragma unroll
        for (int w = 0; w < NW; ++w) v += vpt[w * 256 + tid];
        vpt[tid] = v * nrm[tid];   // own slot only: no race
    }
    __syncthreads();

    // ---- acc[d] = sum_j v'_j * Hn[j,d], 4-way split over j ----
    if (tid < 512) {
        const int d = tid & 127, jb = (tid >> 7) * 64;
        float a = 0.f;
        #pragma unroll 4
        for (int jx = 0; jx < 64; ++jx) {
            const int j = jb + jx;
            const float vj = vpt[j];
            const uint32_t off = (uint32_t)j * SRSB + (uint32_t)d * 2;
            a += vj * __bfloat162float(*(__nv_bfloat16*)(smc + SM_HN + off));
        }
        smf[SM_ACC / 4 + tid] = a;
    }
    __syncthreads();
    if (tid < D_) {   // h_last -> CX_HL (Hn region dead after the sync above)
        float s = smf[SM_ACC / 4 + tid] + smf[SM_ACC / 4 + 128 + tid]
                + smf[SM_ACC / 4 + 256 + tid] + smf[SM_ACC / 4 + 384 + tid];
        #pragma unroll
        for (int w = 0; w < NW; ++w) s += smf[SM_DP / 4 + w * D_ + tid];
        smf[CX_HL / 4 + tid] = s;
    }
    __syncthreads();

    // ---- cross cosine-attention over hist_2 + relu(h @ W) ----
    if (tid < 32) {
        float s = 0.f;
        #pragma unroll
        for (int c = 0; c < 4; ++c) { float v = smf[CX_HL / 4 + tid + 32 * c]; s += v * v; }
        #pragma unroll
        for (int o = 16; o; o >>= 1) s += __shfl_xor_sync(0xffffffffu, s, o);
        if (tid == 0) smf[CX_IQ / 4] = rsqrtf(s + EPSF);
    }
    __syncthreads();
    {
        const float invq = smf[CX_IQ / 4];
        const float* H2 = h2 + (size_t)b * 256 * D_;
        const float q0 = smf[CX_HL / 4 + lane * 4],     q1 = smf[CX_HL / 4 + lane * 4 + 1];
        const float q2 = smf[CX_HL / 4 + lane * 4 + 2], q3 = smf[CX_HL / 4 + lane * 4 + 3];
        float a0 = 0.f, a1 = 0.f, a2 = 0.f, a3 = 0.f, wp = 0.f;
        for (int k = wid; k < 256; k += NW) {
            float4 v = ((const float4*)(H2 + k * D_))[lane];
            float dot = v.x * q0 + v.y * q1 + v.z * q2 + v.w * q3;
            float nk  = v.x * v.x + v.y * v.y + v.z * v.z + v.w * v.w;
            #pragma unroll
            for (int o = 16; o; o >>= 1) {
                dot += __shfl_xor_sync(0xffffffffu, dot, o);
                nk  += __shfl_xor_sync(0xffffffffu, nk,  o);
            }
            float w = __expf(dot * rsqrtf(nk + EPSF) * invq)
                    * ((seq1[b * 256 + k] != 0) ? 1.f : 0.f);
            wp += w;
            a0 += w * v.x; a1 += w * v.y; a2 += w * v.z; a3 += w * v.w;
        }
        if (lane == 0) smf[CX_WS / 4 + wid] = wp;
        smf[CX_HA / 4 + wid * D_ + lane * 4]     = a0;
        smf[CX_HA / 4 + wid * D_ + lane * 4 + 1] = a1;
        smf[CX_HA / 4 + wid * D_ + lane * 4 + 2] = a2;
        smf[CX_HA / 4 + wid * D_ + lane * 4 + 3] = a3;
    }
    __syncthreads();
    if (tid < D_) {
        float ws = 0.f, s = 0.f;
        #pragma unroll
        for (int w = 0; w < NW; ++w) { ws += smf[CX_WS / 4 + w]; s += smf[CX_HA / 4 + w * D_ + tid]; }
        smf[CX_HV / 4 + tid] = s / ws;
    }
    __syncthreads();

    // ---- out = relu(hv @ W), 4-way split over d then combine ----
    if (tid < 512) {
        const int col = tid & 127, q = tid >> 7;
        float o = 0.f;
        #pragma unroll 8
        for (int dx = 0; dx < 32; ++dx) {
            const int d = q * 32 + dx;
            o += smf[CX_HV / 4 + d] * W[d * D_ + col];
        }
        smf[CX_HA / 4 + q * D_ + col] = o;   // reuse CX_HA (dead after hv combine)
    }
    __syncthreads();
    if (tid < D_) {
        float o = smf[CX_HA / 4 + tid] + smf[CX_HA / 4 + 128 + tid]
                + smf[CX_HA / 4 + 256 + tid] + smf[CX_HA / 4 + 384 + tid];
        out[b * D_ + tid] = fmaxf(o, 0.f);
    }
}

extern "C" void kernel_launch(void* const* d_in, const int* in_sizes, int n_in,
                              void* d_out, int out_size)
{
    const int*   seq  = (const int*)d_in[0];
    const int*   last = (const int*)d_in[1];
    const int*   seq1 = (const int*)d_in[2];
    const float* h1   = (const float*)d_in[3];
    const float* h2   = (const float*)d_in[4];
    const float* W    = (const float*)d_in[5];
    float* out = (float*)d_out;

    cudaFuncSetAttribute(fused_itd, cudaFuncAttributeMaxDynamicSharedMemorySize, SM_TOT);
    fused_itd<<<B_, NT, SM_TOT>>>(seq, last, seq1, h1, h2, W, out);
}

// round 16
// speedup vs baseline: 1.6817x; 1.1077x over previous
#include <cuda_runtime.h>
#include <cuda_bf16.h>
#include <cstdint>

#define B_   512
#define L_   256
#define D_   128
#define EPSF 0.01f
#define NW   32             // warps per CTA
#define NT   1024           // threads per CTA
#define SRSB 272            // bf16 row stride in bytes: ldmatrix conflict-free

// ---- smem byte offsets ----
#define SM_HN   0           // 256 x SRSB bf16 normalized rows
#define SM_NRM  69632       // 256 f32  ||h||
#define SM_M    70656       // 256 f32 key mask
#define SM_SEL  71680       // 256 f32 (mask*last)
#define SM_A    72704       // 256 f32 a_i = sel_i / wsum_i
#define SM_WSP  73728       // 32 x 256 f32 per-warp wsum partials
#define SM_VPT  106496      // 32 x 256 f32 per-warp v partials
#define SM_DP   139264      // 32 x 128 f32 direct-term partials
#define SM_ACC  155648      // 512 f32
#define SM_TOT  157696
// cross-phase aliases (Hn region dead by then)
#define CX_HL   0           // 128 f32
#define CX_WS   512         // 32 f32
#define CX_HA   1024        // 32 x 128 f32
#define CX_HV   17408       // 128 f32
#define CX_IQ   17920       // 1 f32

// packed (tr<<4 | tc) for upper-triangular job index j in [0,136)
__device__ __constant__ unsigned char TRTAB[136] = {
    0x00,0x01,0x02,0x03,0x04,0x05,0x06,0x07,0x08,0x09,0x0A,0x0B,0x0C,0x0D,0x0E,0x0F,
    0x11,0x12,0x13,0x14,0x15,0x16,0x17,0x18,0x19,0x1A,0x1B,0x1C,0x1D,0x1E,0x1F,
    0x22,0x23,0x24,0x25,0x26,0x27,0x28,0x29,0x2A,0x2B,0x2C,0x2D,0x2E,0x2F,
    0x33,0x34,0x35,0x36,0x37,0x38,0x39,0x3A,0x3B,0x3C,0x3D,0x3E,0x3F,
    0x44,0x45,0x46,0x47,0x48,0x49,0x4A,0x4B,0x4C,0x4D,0x4E,0x4F,
    0x55,0x56,0x57,0x58,0x59,0x5A,0x5B,0x5C,0x5D,0x5E,0x5F,
    0x66,0x67,0x68,0x69,0x6A,0x6B,0x6C,0x6D,0x6E,0x6F,
    0x77,0x78,0x79,0x7A,0x7B,0x7C,0x7D,0x7E,0x7F,
    0x88,0x89,0x8A,0x8B,0x8C,0x8D,0x8E,0x8F,
    0x99,0x9A,0x9B,0x9C,0x9D,0x9E,0x9F,
    0xAA,0xAB,0xAC,0xAD,0xAE,0xAF,
    0xBB,0xBC,0xBD,0xBE,0xBF,
    0xCC,0xCD,0xCE,0xCF,
    0xDD,0xDE,0xDF,
    0xEE,0xEF,
    0xFF
};

__device__ __forceinline__ uint32_t smem_u32(const void* p) {
    uint32_t a;
    asm("{ .reg .u64 t; cvta.to.shared.u64 t, %1; cvt.u32.u64 %0, t; }" : "=r"(a) : "l"(p));
    return a;
}
#define LDSM4(r, addr) \
    asm volatile("ldmatrix.sync.aligned.m8n8.x4.shared.b16 {%0,%1,%2,%3}, [%4];" \
        : "=r"((r)[0]), "=r"((r)[1]), "=r"((r)[2]), "=r"((r)[3]) : "r"(addr))
#define MMA16816(c, a, b0, b1) \
    asm volatile("mma.sync.aligned.m16n8k16.row.col.f32.bf16.bf16.f32 " \
        "{%0,%1,%2,%3}, {%4,%5,%6,%7}, {%8,%9}, {%0,%1,%2,%3};" \
        : "+f"((c)[0]), "+f"((c)[1]), "+f"((c)[2]), "+f"((c)[3]) \
        : "r"((a)[0]), "r"((a)[1]), "r"((a)[2]), "r"((a)[3]), "r"(b0), "r"(b1))
#define BFLY(x, o) x += __shfl_xor_sync(0xffffffffu, x, o)

__device__ __forceinline__ uint16_t bf16b(float x) {
    return __nv_bfloat16_raw(__float2bfloat16_rn(x)).x;
}
__device__ __forceinline__ uint32_t bfbits(float x) {
    return (uint32_t)__nv_bfloat16_raw(__float2bfloat16_rn(x)).x;
}
__device__ __forceinline__ float bflo(uint32_t p) { return __uint_as_float(p << 16); }
__device__ __forceinline__ float bfhi(uint32_t p) { return __uint_as_float(p & 0xFFFF0000u); }

__global__ __launch_bounds__(NT, 1)
void fused_itd(const int* __restrict__ seq, const int* __restrict__ last,
               const int* __restrict__ seq1, const float* __restrict__ h1,
               const float* __restrict__ h2, const float* __restrict__ W,
               float* __restrict__ out)
{
    extern __shared__ unsigned char smraw[];
    float* smf = (float*)smraw;
    unsigned char* smc = smraw;
    const uint32_t sb = smem_u32(smraw);
    const int b = blockIdx.x, tid = threadIdx.x, wid = tid >> 5, lane = tid & 31;

    float* nrm  = smf + SM_NRM / 4;
    float* mz   = smf + SM_M / 4;
    float* selv = smf + SM_SEL / 4;
    float* av   = smf + SM_A / 4;
    float* wsp  = smf + SM_WSP / 4;
    float* vpt  = smf + SM_VPT / 4;

    // ---- masks / zero-init of partial arrays ----
    if (tid < 256) {
        int sv = seq[b * L_ + tid], lv = last[b * L_ + tid];
        float m = (sv != 0) ? 1.f : 0.f;
        mz[tid]   = m;
        selv[tid] = m * (float)lv;
    }
    for (int i = tid; i < 2 * NW * 256; i += NT) wsp[i] = 0.f;   // wsp + vpt contiguous
    __syncthreads();

    // ---- load hist_1[b]: normalize rows -> bf16 Hn, keep ||h||, direct term ----
    const float4* src4 = (const float4*)(h1 + (size_t)b * L_ * D_);
    const int d0 = lane * 4;
    float ds0 = 0.f, ds1 = 0.f, ds2 = 0.f, ds3 = 0.f;
    for (int i = wid; i < 256; i += NW) {
        const float4 v = src4[i * 32 + lane];
        float np = v.x * v.x + v.y * v.y + v.z * v.z + v.w * v.w;
        #pragma unroll
        for (int o = 16; o; o >>= 1) np += __shfl_xor_sync(0xffffffffu, np, o);
        const float invf = rsqrtf(np + EPSF);
        if (lane == 0) nrm[i] = sqrtf(np + EPSF);
        const float se = selv[i];
        ds0 += se * v.x; ds1 += se * v.y; ds2 += se * v.z; ds3 += se * v.w;

        uint16_t hn0 = bf16b(v.x * invf), hn1 = bf16b(v.y * invf);
        uint16_t hn2 = bf16b(v.z * invf), hn3 = bf16b(v.w * invf);
        uint32_t off = (uint32_t)i * SRSB + (uint32_t)d0 * 2;
        *(uint2*)(smc + SM_HN + off) = make_uint2(
            (uint32_t)hn0 | ((uint32_t)hn1 << 16), (uint32_t)hn2 | ((uint32_t)hn3 << 16));
    }
    smf[SM_DP / 4 + wid * D_ + d0 + 0] = ds0;
    smf[SM_DP / 4 + wid * D_ + d0 + 1] = ds1;
    smf[SM_DP / 4 + wid * D_ + d0 + 2] = ds2;
    smf[SM_DP / 4 + wid * D_ + d0 + 3] = ds3;
    __syncthreads();

    // =======================================================================
    // Self attention on upper-triangular 16x16 tiles (136 jobs, 32 warps).
    // cos directly from one bf16 MMA of normalized rows. Warp w owns 5 (w<8)
    // or 4 contiguous tiles, processed in groups of <=2 (A-fragment reuse).
    // e-tiles cached bf16x2-PACKED across the wsum barrier; wsum uses the
    // rounded values so normalization stays consistent.
    // =======================================================================
    const int lo  = (wid < 8) ? wid * 5 : 40 + (wid - 8) * 4;
    const int len = (wid < 8) ? 5 : 4;

    uint32_t etp[20];   // up to 5 tiles x 4 bf16x2 regs

    #pragma unroll
    for (int g = 0; g < 3; ++g) {
        const int cnt = len - 2 * g;          // 2,2,1 (len5) / 2,2,0 (len4)
        if (cnt > 0) {
            const int gb = lo + 2 * g;

            uint32_t aB[2], bB[2];
            int ldm = 0;
            {
                int prev_tr = -1;
                #pragma unroll
                for (int s = 0; s < 2; ++s) {
                    const int j = gb + s;
                    const int pk = TRTAB[(j < 136) ? j : 135];
                    const int tr = pk >> 4, tc = pk & 15;
                    aB[s] = sb + SM_HN
                        + (uint32_t)(tr * 16 + (lane & 7) + (((lane >> 3) & 1) * 8)) * SRSB
                        + (uint32_t)((lane >> 4) * 8) * 2;
                    bB[s] = sb + SM_HN
                        + (uint32_t)(tc * 16 + (lane & 7) + ((lane >> 4) * 8)) * SRSB
                        + (uint32_t)((lane >> 3) & 1) * 16;
                    if (s < cnt && tr != prev_tr) ldm |= 1 << s;
                    if (s < cnt) prev_tr = tr;
                }
            }

            float acc[16];
            #pragma unroll
            for (int i = 0; i < 16; ++i) acc[i] = 0.f;

            for (int k = 0; k < 8; ++k) {
                uint32_t ah[4];
                const uint32_t ko = (uint32_t)k * 32;
                #pragma unroll
                for (int s = 0; s < 2; ++s) {
                    if (s < cnt) {
                        if ((ldm >> s) & 1) LDSM4(ah, aB[s] + ko);
                        uint32_t bh[4];
                        LDSM4(bh, bB[s] + ko);
                        float* e = &acc[8 * s];
                        MMA16816(e,     ah, bh[0], bh[1]);
                        MMA16816(e + 4, ah, bh[2], bh[3]);
                    }
                }
            }

            // group epilogue: exp -> bf16 round -> pack + wsum contributions
            #pragma unroll
            for (int s = 0; s < 2; ++s) {
                if (s < cnt) {
                    const int pk = TRTAB[gb + s];
                    const int tr = pk >> 4, tc = pk & 15;
                    float* a = &acc[8 * s];
                    const int r0 = tr * 16 + (lane >> 2), r1 = r0 + 8;
                    const int c0 = tc * 16 + (lane & 3) * 2;

                    float e[8];
                    uint32_t bits[8];
                    #pragma unroll
                    for (int i = 0; i < 8; ++i) {
                        bits[i] = bfbits(__expf(a[i]));
                        e[i] = __uint_as_float(bits[i] << 16);
                    }
                    const int ti = 2 * g + s;   // 0..4
                    etp[4 * ti + 0] = bits[0] | (bits[1] << 16);
                    etp[4 * ti + 1] = bits[2] | (bits[3] << 16);
                    etp[4 * ti + 2] = bits[4] | (bits[5] << 16);
                    etp[4 * ti + 3] = bits[6] | (bits[7] << 16);

                    // direct: ws[r] += sum_c e*m_c
                    const float mc0 = mz[c0], mc1 = mz[c0 + 1], mc8 = mz[c0 + 8], mc9 = mz[c0 + 9];
                    float rs0 = e[0] * mc0 + e[1] * mc1 + e[4] * mc8 + e[5] * mc9;
                    float rs1 = e[2] * mc0 + e[3] * mc1 + e[6] * mc8 + e[7] * mc9;
                    BFLY(rs0, 1); BFLY(rs0, 2);
                    BFLY(rs1, 1); BFLY(rs1, 2);
                    if ((lane & 3) == 0) {
                        wsp[wid * 256 + r0] += rs0;
                        wsp[wid * 256 + r1] += rs1;
                    }
                    // mirror: ws[c] += sum_r e*m_r  (skip on diagonal tiles)
                    if (tr != tc) {
                        const float mr0 = mz[r0], mr1 = mz[r1];
                        float cs0 = e[0] * mr0 + e[2] * mr1;
                        float cs1 = e[1] * mr0 + e[3] * mr1;
                        float cs8 = e[4] * mr0 + e[6] * mr1;
                        float cs9 = e[5] * mr0 + e[7] * mr1;
                        BFLY(cs0, 4); BFLY(cs0, 8); BFLY(cs0, 16);
                        BFLY(cs1, 4); BFLY(cs1, 8); BFLY(cs1, 16);
                        BFLY(cs8, 4); BFLY(cs8, 8); BFLY(cs8, 16);
                        BFLY(cs9, 4); BFLY(cs9, 8); BFLY(cs9, 16);
                        if (lane < 4) {
                            const int cb = tc * 16 + lane * 2;
                            wsp[wid * 256 + cb]     += cs0;
                            wsp[wid * 256 + cb + 1] += cs1;
                            wsp[wid * 256 + cb + 8] += cs8;
                            wsp[wid * 256 + cb + 9] += cs9;
                        }
                    }
                }
            }
        }
    }
    __syncthreads();

    // ---- a_i = sel_i / wsum_i ----
    if (tid < 256) {
        float ws = 0.f;
        #pragma unroll
        for (int w = 0; w < NW; ++w) ws += wsp[w * 256 + tid];
        av[tid] = selv[tid] / ws;
    }
    __syncthreads();

    // ---- phase 2: v contributions from packed et (cols direct, rows mirror) ----
    #pragma unroll
    for (int s = 0; s < 5; ++s) {
        if (s < len) {
            const int pk = TRTAB[lo + s];
            const int tr = pk >> 4, tc = pk & 15;
            float e[8];
            e[0] = bflo(etp[4 * s + 0]); e[1] = bfhi(etp[4 * s + 0]);
            e[2] = bflo(etp[4 * s + 1]); e[3] = bfhi(etp[4 * s + 1]);
            e[4] = bflo(etp[4 * s + 2]); e[5] = bfhi(etp[4 * s + 2]);
            e[6] = bflo(etp[4 * s + 3]); e[7] = bfhi(etp[4 * s + 3]);
            const int r0 = tr * 16 + (lane >> 2), r1 = r0 + 8;
            const int c0 = tc * 16 + (lane & 3) * 2;

            // direct: v[c] += m_c * sum_r a_r e_rc
            const float ar0 = av[r0], ar1 = av[r1];
            float pc0 = ar0 * e[0] + ar1 * e[2];
            float pc1 = ar0 * e[1] + ar1 * e[3];
            float pc8 = ar0 * e[4] + ar1 * e[6];
            float pc9 = ar0 * e[5] + ar1 * e[7];
            BFLY(pc0, 4); BFLY(pc0, 8); BFLY(pc0, 16);
            BFLY(pc1, 4); BFLY(pc1, 8); BFLY(pc1, 16);
            BFLY(pc8, 4); BFLY(pc8, 8); BFLY(pc8, 16);
            BFLY(pc9, 4); BFLY(pc9, 8); BFLY(pc9, 16);
            if (lane < 4) {
                const int cb = tc * 16 + lane * 2;
                vpt[wid * 256 + cb]     += pc0 * mz[cb];
                vpt[wid * 256 + cb + 1] += pc1 * mz[cb + 1];
                vpt[wid * 256 + cb + 8] += pc8 * mz[cb + 8];
                vpt[wid * 256 + cb + 9] += pc9 * mz[cb + 9];
            }
            // mirror: v[r] += m_r * sum_c a_c e_rc  (skip on diagonal tiles)
            if (tr != tc) {
                const float ac0 = av[c0], ac1 = av[c0 + 1];
                const float ac8 = av[c0 + 8], ac9 = av[c0 + 9];
                float qr0 = ac0 * e[0] + ac1 * e[1] + ac8 * e[4] + ac9 * e[5];
                float qr1 = ac0 * e[2] + ac1 * e[3] + ac8 * e[6] + ac9 * e[7];
                BFLY(qr0, 1); BFLY(qr0, 2);
                BFLY(qr1, 1); BFLY(qr1, 2);
                if ((lane & 3) == 0) {
                    vpt[wid * 256 + r0] += qr0 * mz[r0];
                    vpt[wid * 256 + r1] += qr1 * mz[r1];
                }
            }
        }
    }
    __syncthreads();

    // ---- v = sum of warp partials, rescaled by ||h_j|| (Hn -> h recovery) ----
    if (tid < 256) {
        float v = 0.f;
        #pragma unroll
        for (int w = 0; w < NW; ++w) v += vpt[w * 256 + tid];
        vpt[tid] = v * nrm[tid];   // own slot only: no race
    }
    __syncthreads();

    // ---- acc[d] = sum_j v'_j * Hn[j,d], 4-way split over j ----
    if (tid < 512) {
        const int d = tid & 127, jb = (tid >> 7) * 64;
        float a = 0.f;
        #pragma unroll 4
        for (int jx = 0; jx < 64; ++jx) {
            const int j = jb + jx;
            const float vj = vpt[j];
            const uint32_t off = (uint32_t)j * SRSB + (uint32_t)d * 2;
            a += vj * __bfloat162float(*(__nv_bfloat16*)(smc + SM_HN + off));
        }
        smf[SM_ACC / 4 + tid] = a;
    }
    __syncthreads();
    if (tid < D_) {   // h_last -> CX_HL (Hn region dead after the sync above)
        float s = smf[SM_ACC / 4 + tid] + smf[SM_ACC / 4 + 128 + tid]
                + smf[SM_ACC / 4 + 256 + tid] + smf[SM_ACC / 4 + 384 + tid];
        #pragma unroll
        for (int w = 0; w < NW; ++w) s += smf[SM_DP / 4 + w * D_ + tid];
        smf[CX_HL / 4 + tid] = s;
    }
    __syncthreads();

    // ---- cross cosine-attention over hist_2 + relu(h @ W) ----
    if (tid < 32) {
        float s = 0.f;
        #pragma unroll
        for (int c = 0; c < 4; ++c) { float v = smf[CX_HL / 4 + tid + 32 * c]; s += v * v; }
        #pragma unroll
        for (int o = 16; o; o >>= 1) s += __shfl_xor_sync(0xffffffffu, s, o);
        if (tid == 0) smf[CX_IQ / 4] = rsqrtf(s + EPSF);
    }
    __syncthreads();
    {
        const float invq = smf[CX_IQ / 4];
        const float* H2 = h2 + (size_t)b * 256 * D_;
        const float q0 = smf[CX_HL / 4 + lane * 4],     q1 = smf[CX_HL / 4 + lane * 4 + 1];
        const float q2 = smf[CX_HL / 4 + lane * 4 + 2], q3 = smf[CX_HL / 4 + lane * 4 + 3];
        float a0 = 0.f, a1 = 0.f, a2 = 0.f, a3 = 0.f, wp = 0.f;
        for (int k = wid; k < 256; k += NW) {
            float4 v = ((const float4*)(H2 + k * D_))[lane];
            float dot = v.x * q0 + v.y * q1 + v.z * q2 + v.w * q3;
            float nk  = v.x * v.x + v.y * v.y + v.z * v.z + v.w * v.w;
            #pragma unroll
            for (int o = 16; o; o >>= 1) {
                dot += __shfl_xor_sync(0xffffffffu, dot, o);
                nk  += __shfl_xor_sync(0xffffffffu, nk,  o);
            }
            float w = __expf(dot * rsqrtf(nk + EPSF) * invq)
                    * ((seq1[b * 256 + k] != 0) ? 1.f : 0.f);
            wp += w;
            a0 += w * v.x; a1 += w * v.y; a2 += w * v.z; a3 += w * v.w;
        }
        if (lane == 0) smf[CX_WS / 4 + wid] = wp;
        smf[CX_HA / 4 + wid * D_ + lane * 4]     = a0;
        smf[CX_HA / 4 + wid * D_ + lane * 4 + 1] = a1;
        smf[CX_HA / 4 + wid * D_ + lane * 4 + 2] = a2;
        smf[CX_HA / 4 + wid * D_ + lane * 4 + 3] = a3;
    }
    __syncthreads();
    if (tid < D_) {
        float ws = 0.f, s = 0.f;
        #pragma unroll
        for (int w = 0; w < NW; ++w) { ws += smf[CX_WS / 4 + w]; s += smf[CX_HA / 4 + w * D_ + tid]; }
        smf[CX_HV / 4 + tid] = s / ws;
    }
    __syncthreads();

    // ---- out = relu(hv @ W), 4-way split over d then combine ----
    if (tid < 512) {
        const int col = tid & 127, q = tid >> 7;
        float o = 0.f;
        #pragma unroll 8
        for (int dx = 0; dx < 32; ++dx) {
            const int d = q * 32 + dx;
            o += smf[CX_HV / 4 + d] * W[d * D_ + col];
        }
        smf[CX_HA / 4 + q * D_ + col] = o;   // reuse CX_HA (dead after hv combine)
    }
    __syncthreads();
    if (tid < D_) {
        float o = smf[CX_HA / 4 + tid] + smf[CX_HA / 4 + 128 + tid]
                + smf[CX_HA / 4 + 256 + tid] + smf[CX_HA / 4 + 384 + tid];
        out[b * D_ + tid] = fmaxf(o, 0.f);
    }
}

extern "C" void kernel_launch(void* const* d_in, const int* in_sizes, int n_in,
                              void* d_out, int out_size)
{
    const int*   seq  = (const int*)d_in[0];
    const int*   last = (const int*)d_in[1];
    const int*   seq1 = (const int*)d_in[2];
    const float* h1   = (const float*)d_in[3];
    const float* h2   = (const float*)d_in[4];
    const float* W    = (const float*)d_in[5];
    float* out = (float*)d_out;

    cudaFuncSetAttribute(fused_itd, cudaFuncAttributeMaxDynamicSharedMemorySize, SM_TOT);
    fused_itd<<<B_, NT, SM_TOT>>>(seq, last, seq1, h1, h2, W, out);
}